// round 2
// baseline (speedup 1.0000x reference)
#include <cuda_runtime.h>

#define NF 510
#define BB 32
#define DD 64
#define HH 4
#define HD 256   // H*D

// Scratch (static device allocations are the sanctioned workaround)
__device__ float g_xt[(size_t)BB * NF * HD];     // (b, n, h*64+d)
__device__ float g_si[BB * HH * NF];
__device__ float g_sj[BB * HH * NF];
__device__ float g_out[(size_t)BB * NF * DD];

// ---------------------------------------------------------------------------
// K1: xt = x @ W  (plus s_i, s_j head scores). 4 rows per block.
// ---------------------------------------------------------------------------
__global__ void k1_proj(const float* __restrict__ x, const float* __restrict__ W,
                        const float* __restrict__ attw) {
    int bn0 = blockIdx.x << 2;          // 4 consecutive flat (b,n) rows
    int tid = threadIdx.x;              // 256 threads, col = tid
    __shared__ __align__(16) float xs[DD][4];
    __shared__ float red[4][8][2];

    xs[tid & 63][tid >> 6] = x[(size_t)bn0 * DD + tid];
    __syncthreads();

    float a0 = 0.f, a1 = 0.f, a2 = 0.f, a3 = 0.f;
#pragma unroll
    for (int d = 0; d < DD; d++) {
        float wv = W[d * HD + tid];
        float4 xv = *reinterpret_cast<const float4*>(xs[d]);
        a0 = fmaf(xv.x, wv, a0);
        a1 = fmaf(xv.y, wv, a1);
        a2 = fmaf(xv.z, wv, a2);
        a3 = fmaf(xv.w, wv, a3);
    }
    g_xt[(size_t)(bn0 + 0) * HD + tid] = a0;
    g_xt[(size_t)(bn0 + 1) * HD + tid] = a1;
    g_xt[(size_t)(bn0 + 2) * HD + tid] = a2;
    g_xt[(size_t)(bn0 + 3) * HD + tid] = a3;

    int h = tid >> 6, d = tid & 63;
    float w1 = attw[h * 128 + d];
    float w2 = attw[h * 128 + 64 + d];
    float accs[4] = {a0, a1, a2, a3};
#pragma unroll
    for (int r = 0; r < 4; r++) {
        float v1 = accs[r] * w1;
        float v2 = accs[r] * w2;
#pragma unroll
        for (int o = 16; o; o >>= 1) {
            v1 += __shfl_xor_sync(0xffffffffu, v1, o);
            v2 += __shfl_xor_sync(0xffffffffu, v2, o);
        }
        if ((tid & 31) == 0) { red[r][tid >> 5][0] = v1; red[r][tid >> 5][1] = v2; }
    }
    __syncthreads();
    if (tid < 16) {
        int r = tid >> 2, hh = tid & 3;
        int bn = bn0 + r;
        int b = bn / NF, n = bn - b * NF;
        g_si[(b * HH + hh) * NF + n] = red[r][2 * hh][0] + red[r][2 * hh + 1][0];
        g_sj[(b * HH + hh) * NF + n] = red[r][2 * hh][1] + red[r][2 * hh + 1][1];
    }
}

// ---------------------------------------------------------------------------
// Block reductions (256 threads)
// ---------------------------------------------------------------------------
__device__ __forceinline__ float blockMax(float v, volatile float* red) {
#pragma unroll
    for (int o = 16; o; o >>= 1) v = fmaxf(v, __shfl_xor_sync(0xffffffffu, v, o));
    if ((threadIdx.x & 31) == 0) red[threadIdx.x >> 5] = v;
    __syncthreads();
    float r = red[0];
#pragma unroll
    for (int i = 1; i < 8; i++) r = fmaxf(r, red[i]);
    __syncthreads();
    return r;
}

__device__ __forceinline__ float blockSum(float v, volatile float* red) {
#pragma unroll
    for (int o = 16; o; o >>= 1) v += __shfl_xor_sync(0xffffffffu, v, o);
    if ((threadIdx.x & 31) == 0) red[threadIdx.x >> 5] = v;
    __syncthreads();
    float r = red[0];
#pragma unroll
    for (int i = 1; i < 8; i++) r += red[i];
    __syncthreads();
    return r;
}

// ---------------------------------------------------------------------------
// K2: per (b, n) row — A_eva, conv(A_mean, causal), logits, softmax, write A.
// A_mean rows n-1..n+1 rebuilt on the fly from s_i/s_j (rank-1 structure).
// ---------------------------------------------------------------------------
__global__ void k2_attn(const float* __restrict__ causal,
                        const float* __restrict__ conv_w,
                        const float* __restrict__ conv_b,
                        float* __restrict__ A_out) {
    int n = blockIdx.x, b = blockIdx.y;
    int tid = threadIdx.x;  // 256

    __shared__ float sj[HH][512];
    __shared__ float amean[3][512];   // index m+1; [0] and [511] are zero padding
    __shared__ float caus[3][512];
    __shared__ float cw[72];
    __shared__ float cb[4];
    __shared__ float si_s[3][HH];
    __shared__ float red[8];

    if (tid < 72) cw[tid] = conv_w[tid];
    if (tid >= 96 && tid < 100) cb[tid - 96] = conv_b[tid - 96];
    if (tid >= 128 && tid < 140) {
        int t = tid - 128, rr = t >> 2, h = t & 3;
        int r = n - 1 + rr;
        si_s[rr][h] = (r >= 0 && r < NF) ? g_si[(b * HH + h) * NF + r] : 0.f;
    }
    for (int i = tid; i < HH * NF; i += 256) {
        int h = i / NF, m = i - h * NF;
        sj[h][m] = g_sj[(b * HH + h) * NF + m];
    }
    __syncthreads();

    for (int i = tid; i < 3 * 512; i += 256) {
        int rr = i >> 9, mm = i & 511;
        int r = n - 1 + rr, m = mm - 1;
        float am = 0.f, cz = 0.f;
        if (r >= 0 && r < NF && m >= 0 && m < NF) {
            float a = 0.f;
#pragma unroll
            for (int h = 0; h < HH; h++) {
                float e = si_s[rr][h] + sj[h][m];
                a += (e >= 0.f) ? e : 0.01f * e;
            }
            am = 0.25f * a;
            cz = causal[r * NF + m];
        }
        amean[rr][mm] = am;
        caus[rr][mm] = cz;
    }
    __syncthreads();

    // Logits for m0 = tid and m1 = tid + 256, all heads
    float lg[2][HH];
    int m0 = tid, m1 = tid + 256;
#pragma unroll
    for (int s = 0; s < 2; s++) {
        int m = s ? m1 : m0;
        if (m < NF) {
            float av[3][3], cv[3][3];
#pragma unroll
            for (int rr = 0; rr < 3; rr++)
#pragma unroll
                for (int dj = 0; dj < 3; dj++) {
                    av[rr][dj] = amean[rr][m + dj];   // stacked col (m-1+dj) at +1 offset
                    cv[rr][dj] = caus[rr][m + dj];
                }
#pragma unroll
            for (int h = 0; h < HH; h++) {
                float st = cb[h];
#pragma unroll
                for (int rr = 0; rr < 3; rr++)
#pragma unroll
                    for (int dj = 0; dj < 3; dj++) {
                        st = fmaf(cw[((h * 2 + 0) * 3 + rr) * 3 + dj], av[rr][dj], st);
                        st = fmaf(cw[((h * 2 + 1) * 3 + rr) * 3 + dj], cv[rr][dj], st);
                    }
                float e = si_s[1][h] + sj[h][m];
                float aeva = (e >= 0.f) ? e : 0.01f * e;
                lg[s][h] = 0.1f * aeva + 0.9f * st;
            }
        } else {
#pragma unroll
            for (int h = 0; h < HH; h++) lg[s][h] = -1e30f;
        }
    }

#pragma unroll
    for (int h = 0; h < HH; h++) {
        float mx = blockMax(fmaxf(lg[0][h], lg[1][h]), red);
        float e0 = __expf(lg[0][h] - mx);
        float e1 = (m1 < NF) ? __expf(lg[1][h] - mx) : 0.f;
        float sum = blockSum(e0 + e1, red);
        float inv = __frcp_rn(sum);
        size_t base = ((size_t)(b * HH + h) * NF + n) * NF;
        A_out[base + m0] = e0 * inv;
        if (m1 < NF) A_out[base + m1] = e1 * inv;
    }
}

// ---------------------------------------------------------------------------
// K3: out[b,n,d] = 0.25 * sum_h sum_m A[b,h,n,m] * xt[b,m,h,d]
// 16 n-rows per block; col = tid -> (h,d). Packed fma.rn.f32x2 over row pairs.
// ---------------------------------------------------------------------------
__global__ void k3_apply(const float* __restrict__ A) {
    int b = blockIdx.y;
    int n0 = blockIdx.x << 4;  // 16 rows
    int tid = threadIdx.x;     // 256
    int h = tid >> 6;

    __shared__ __align__(8) float xts[16][HD];
    __shared__ __align__(8) float As[4][16][18];  // [h][j][r], pad 18 (8B-aligned rows, no store conflicts)
    __shared__ float sred[2][256];

    unsigned long long acc2[8];
#pragma unroll
    for (int i = 0; i < 8; i++) acc2[i] = 0ull;

    for (int m0 = 0; m0 < NF; m0 += 16) {
#pragma unroll
        for (int j = 0; j < 16; j++) {
            int m = m0 + j;
            xts[j][tid] = (m < NF) ? g_xt[((size_t)b * NF + m) * HD + tid] : 0.f;
        }
#pragma unroll
        for (int hh = 0; hh < 4; hh++) {
            int r = tid >> 4, j = tid & 15;        // j fastest -> coalesced global reads
            int n = n0 + r, m = m0 + j;
            float v = 0.f;
            if (n < NF && m < NF)
                v = A[((size_t)(b * HH + hh) * NF + n) * NF + m];
            As[hh][j][r] = v;
        }
        __syncthreads();
#pragma unroll
        for (int j = 0; j < 16; j++) {
            float xv = xts[j][tid];
            unsigned long long xv2;
            asm("mov.b64 %0, {%1, %2};" : "=l"(xv2) : "f"(xv), "f"(xv));
#pragma unroll
            for (int r2 = 0; r2 < 8; r2++) {
                unsigned long long a2 =
                    *reinterpret_cast<const unsigned long long*>(&As[h][j][2 * r2]);
                asm("fma.rn.f32x2 %0, %1, %2, %0;" : "+l"(acc2[r2]) : "l"(a2), "l"(xv2));
            }
        }
        __syncthreads();
    }

    // reduce over heads (threads tid, tid+64, tid+128, tid+192) and write
#pragma unroll
    for (int r2 = 0; r2 < 8; r2++) {
        float lo, hi;
        asm("mov.b64 {%0, %1}, %2;" : "=f"(lo), "=f"(hi) : "l"(acc2[r2]));
        sred[0][tid] = lo;
        sred[1][tid] = hi;
        __syncthreads();
        if (tid < 128) {
            int p = tid >> 6, dd = tid & 63;
            int n = n0 + 2 * r2 + p;
            if (n < NF) {
                float s = sred[p][dd] + sred[p][dd + 64] + sred[p][dd + 128] + sred[p][dd + 192];
                g_out[((size_t)b * NF + n) * DD + dd] = 0.25f * s;
            }
        }
        __syncthreads();
    }
}

// ---------------------------------------------------------------------------
// K4: g = out @ fcg_w + fcg_b; GLU; residual; LayerNorm. One (b,n) per block.
// ---------------------------------------------------------------------------
__global__ void k4_glu_ln(const float* __restrict__ x,
                          const float* __restrict__ fw, const float* __restrict__ fb,
                          const float* __restrict__ lgm, const float* __restrict__ lbt,
                          float* __restrict__ y) {
    int bn = blockIdx.x;
    int tid = threadIdx.x;  // 128
    __shared__ float orow[DD];
    __shared__ float gsh[128];
    __shared__ float red[4];

    if (tid < DD) orow[tid] = g_out[(size_t)bn * DD + tid];
    __syncthreads();

    float acc = fb[tid];
#pragma unroll
    for (int d = 0; d < DD; d++) acc = fmaf(orow[d], fw[d * 128 + tid], acc);
    gsh[tid] = acc;
    __syncthreads();

    float yv = 0.f;
    if (tid < DD) {
        float a = gsh[tid], bg = gsh[tid + DD];
        float sig = 1.f / (1.f + __expf(-bg));
        yv = fmaf(a, sig, x[(size_t)bn * DD + tid]);
    }

    float s = (tid < DD) ? yv : 0.f;
#pragma unroll
    for (int o = 16; o; o >>= 1) s += __shfl_xor_sync(0xffffffffu, s, o);
    if ((tid & 31) == 0) red[tid >> 5] = s;
    __syncthreads();
    float mu = (red[0] + red[1] + red[2] + red[3]) * (1.f / 64.f);
    __syncthreads();

    float dv = (tid < DD) ? (yv - mu) : 0.f;
    float q = dv * dv;
#pragma unroll
    for (int o = 16; o; o >>= 1) q += __shfl_xor_sync(0xffffffffu, q, o);
    if ((tid & 31) == 0) red[tid >> 5] = q;
    __syncthreads();
    float var = (red[0] + red[1] + red[2] + red[3]) * (1.f / 64.f);

    if (tid < DD) {
        float out = dv * rsqrtf(var + 1e-5f) * lgm[tid] + lbt[tid];
        y[(size_t)bn * DD + tid] = out;
    }
}

// ---------------------------------------------------------------------------
extern "C" void kernel_launch(void* const* d_in, const int* in_sizes, int n_in,
                              void* d_out, int out_size) {
    const float* x      = (const float*)d_in[0];
    const float* causal = (const float*)d_in[1];
    const float* W      = (const float*)d_in[2];
    const float* attw   = (const float*)d_in[3];
    const float* conv_w = (const float*)d_in[4];
    const float* conv_b = (const float*)d_in[5];
    const float* fcg_w  = (const float*)d_in[6];
    const float* fcg_b  = (const float*)d_in[7];
    const float* ln_g   = (const float*)d_in[8];
    const float* ln_b   = (const float*)d_in[9];

    float* y = (float*)d_out;
    float* A = (float*)d_out + (size_t)BB * NF * DD;   // (y, A) flattened in order

    k1_proj<<<(BB * NF) / 4, 256>>>(x, W, attw);
    k2_attn<<<dim3(NF, BB), 256>>>(causal, conv_w, conv_b, A);
    k3_apply<<<dim3((NF + 15) / 16, BB), 256>>>(A);
    k4_glu_ln<<<BB * NF, 128>>>(x, fcg_w, fcg_b, ln_g, ln_b, y);
}

// round 4
// speedup vs baseline: 1.1857x; 1.1857x over previous
#include <cuda_runtime.h>

#define NF 510
#define BB 32
#define DD 64
#define HH 4
#define HD 256   // H*D

typedef unsigned long long ull;

// Scratch (static device arrays are the sanctioned workaround)
__device__ float g_xt[(size_t)BB * NF * HD];     // (b, n, h*64+d)
__device__ float g_si[BB * HH * NF];
__device__ float g_sj[BB * HH * NF];
__device__ float g_out[(size_t)BB * NF * DD];
__device__ float g_cconv[(size_t)HH * NF * NF];  // conv(causal)+bias, b-independent

__device__ __forceinline__ ull pack2(float a, float b) {
    ull r; asm("mov.b64 %0, {%1, %2};" : "=l"(r) : "f"(a), "f"(b)); return r;
}
__device__ __forceinline__ void fma2(ull& acc, ull a, ull b) {
    asm("fma.rn.f32x2 %0, %1, %2, %0;" : "+l"(acc) : "l"(a), "l"(b));
}
__device__ __forceinline__ float2 unpack2(ull v) {
    float2 f; asm("mov.b64 {%0, %1}, %2;" : "=f"(f.x), "=f"(f.y) : "l"(v)); return f;
}

// ---------------------------------------------------------------------------
// K1: xt = x @ W  (+ s_i, s_j head scores). 8 rows/block, f32x2 row pairs.
// ---------------------------------------------------------------------------
__global__ void k1_proj(const float* __restrict__ x, const float* __restrict__ W,
                        const float* __restrict__ attw) {
    int bn0 = blockIdx.x << 3;
    int tid = threadIdx.x;              // 256, col = tid
    __shared__ __align__(8) float xs[DD][10];   // [d][row], pad 10 (pairs 8B-aligned)
    __shared__ float red[8][8][2];

#pragma unroll
    for (int k = 0; k < 2; k++) {
        int i = tid + (k << 8);
        int r = i >> 6, d = i & 63;
        xs[d][r] = x[(size_t)(bn0 + r) * DD + d];
    }
    __syncthreads();

    ull acc[4] = {0ull, 0ull, 0ull, 0ull};
#pragma unroll
    for (int d = 0; d < DD; d++) {
        float wv = W[d * HD + tid];
        ull wv2 = pack2(wv, wv);
#pragma unroll
        for (int p = 0; p < 4; p++) {
            ull xp = *reinterpret_cast<const ull*>(&xs[d][2 * p]);
            fma2(acc[p], xp, wv2);
        }
    }
    float accs[8];
#pragma unroll
    for (int p = 0; p < 4; p++) {
        float2 v = unpack2(acc[p]);
        accs[2 * p] = v.x; accs[2 * p + 1] = v.y;
    }
#pragma unroll
    for (int r = 0; r < 8; r++)
        g_xt[(size_t)(bn0 + r) * HD + tid] = accs[r];

    int h = tid >> 6, dd = tid & 63;
    float w1 = attw[h * 128 + dd];
    float w2 = attw[h * 128 + 64 + dd];
    int wid = tid >> 5, lane = tid & 31;
#pragma unroll
    for (int r = 0; r < 8; r++) {
        float v1 = accs[r] * w1;
        float v2 = accs[r] * w2;
#pragma unroll
        for (int o = 16; o; o >>= 1) {
            v1 += __shfl_xor_sync(0xffffffffu, v1, o);
            v2 += __shfl_xor_sync(0xffffffffu, v2, o);
        }
        if (lane == 0) { red[r][wid][0] = v1; red[r][wid][1] = v2; }
    }
    __syncthreads();
    if (tid < 32) {
        int r = tid >> 2, hh = tid & 3;
        int bn = bn0 + r;
        int b = bn / NF, n = bn - b * NF;
        g_si[(b * HH + hh) * NF + n] = red[r][2 * hh][0] + red[r][2 * hh + 1][0];
        g_sj[(b * HH + hh) * NF + n] = red[r][2 * hh][1] + red[r][2 * hh + 1][1];
    }
}

// ---------------------------------------------------------------------------
// K2a: causal-channel conv + bias, b-independent: computed ONCE per (h,n,m).
// ---------------------------------------------------------------------------
__global__ void k2a_cconv(const float* __restrict__ causal,
                          const float* __restrict__ conv_w,
                          const float* __restrict__ conv_b) {
    int n = blockIdx.x;
    int tid = threadIdx.x;  // 256
    __shared__ float caus[3][512];
    __shared__ float cw[72];
    __shared__ float cb[4];

    if (tid < 72) cw[tid] = conv_w[tid];
    if (tid >= 96 && tid < 100) cb[tid - 96] = conv_b[tid - 96];
    for (int i = tid; i < 3 * 512; i += 256) {
        int rr = i >> 9, mm = i & 511;
        int r = n - 1 + rr, m = mm - 1;
        caus[rr][mm] = (r >= 0 && r < NF && m >= 0 && m < NF) ? causal[r * NF + m] : 0.f;
    }
    __syncthreads();

#pragma unroll
    for (int s = 0; s < 2; s++) {
        int m = tid + (s << 8);
        if (m < NF) {
#pragma unroll
            for (int h = 0; h < HH; h++) {
                float st = cb[h];
#pragma unroll
                for (int rr = 0; rr < 3; rr++)
#pragma unroll
                    for (int dj = 0; dj < 3; dj++)
                        st = fmaf(cw[((h * 2 + 1) * 3 + rr) * 3 + dj], caus[rr][m + dj], st);
                g_cconv[((size_t)h * NF + n) * NF + m] = st;
            }
        }
    }
}

// ---------------------------------------------------------------------------
// K2: per (b,n) row: amean rows via rank-1 scores, amean-channel conv,
// logits, softmax (merged 2-round reductions), write A.
// ---------------------------------------------------------------------------
__global__ void k2_attn(const float* __restrict__ conv_w,
                        float* __restrict__ A_out) {
    int n = blockIdx.x, b = blockIdx.y;
    int tid = threadIdx.x;  // 256
    int wid = tid >> 5, lane = tid & 31;

    __shared__ float sj[HH][512];
    __shared__ float amean[3][512];   // index m+1; [0] and [511] zero
    __shared__ float cw0[36];         // amean-channel weights only
    __shared__ float si_s[3][HH];
    __shared__ float redm[HH][8];
    __shared__ float reds_[HH][8];

    if (tid < 36) {
        int h = tid / 9, k = tid - h * 9;
        cw0[tid] = conv_w[h * 18 + k];   // channel 0
    }
    if (tid >= 64 && tid < 76) {
        int t = tid - 64, rr = t >> 2, h = t & 3;
        int r = n - 1 + rr;
        si_s[rr][h] = (r >= 0 && r < NF) ? g_si[(b * HH + h) * NF + r] : 0.f;
    }
    for (int i = tid; i < HH * 512; i += 256) {
        int h = i >> 9, m = i & 511;
        sj[h][m] = (m < NF) ? g_sj[(b * HH + h) * NF + m] : 0.f;
    }
    __syncthreads();

    for (int i = tid; i < 3 * 512; i += 256) {
        int rr = i >> 9, mm = i & 511;
        int r = n - 1 + rr, m = mm - 1;
        float am = 0.f;
        if (r >= 0 && r < NF && m >= 0 && m < NF) {
            float a = 0.f;
#pragma unroll
            for (int h = 0; h < HH; h++) {
                float e = si_s[rr][h] + sj[h][m];
                a += (e >= 0.f) ? e : 0.01f * e;
            }
            am = 0.25f * a;
        }
        amean[rr][mm] = am;
    }
    __syncthreads();

    float lg[2][HH];
#pragma unroll
    for (int s = 0; s < 2; s++) {
        int m = tid + (s << 8);
        if (m < NF) {
            float av[3][3];
#pragma unroll
            for (int rr = 0; rr < 3; rr++)
#pragma unroll
                for (int dj = 0; dj < 3; dj++)
                    av[rr][dj] = amean[rr][m + dj];
#pragma unroll
            for (int h = 0; h < HH; h++) {
                float st = g_cconv[((size_t)h * NF + n) * NF + m];
#pragma unroll
                for (int rr = 0; rr < 3; rr++)
#pragma unroll
                    for (int dj = 0; dj < 3; dj++)
                        st = fmaf(cw0[h * 9 + rr * 3 + dj], av[rr][dj], st);
                float e = si_s[1][h] + sj[h][m];
                float aeva = (e >= 0.f) ? e : 0.01f * e;
                lg[s][h] = fmaf(0.1f, aeva, 0.9f * st);
            }
        } else {
#pragma unroll
            for (int h = 0; h < HH; h++) lg[s][h] = -1e30f;
        }
    }

    // merged max reduction (all heads, one smem round)
    float mx[HH];
#pragma unroll
    for (int h = 0; h < HH; h++) mx[h] = fmaxf(lg[0][h], lg[1][h]);
#pragma unroll
    for (int o = 16; o; o >>= 1)
#pragma unroll
        for (int h = 0; h < HH; h++)
            mx[h] = fmaxf(mx[h], __shfl_xor_sync(0xffffffffu, mx[h], o));
    if (lane == 0)
#pragma unroll
        for (int h = 0; h < HH; h++) redm[h][wid] = mx[h];
    __syncthreads();

    float e0[HH], e1[HH], sm[HH];
    int m1 = tid + 256;
#pragma unroll
    for (int h = 0; h < HH; h++) {
        float g = redm[h][0];
#pragma unroll
        for (int i = 1; i < 8; i++) g = fmaxf(g, redm[h][i]);
        e0[h] = __expf(lg[0][h] - g);
        e1[h] = (m1 < NF) ? __expf(lg[1][h] - g) : 0.f;
        sm[h] = e0[h] + e1[h];
    }
#pragma unroll
    for (int o = 16; o; o >>= 1)
#pragma unroll
        for (int h = 0; h < HH; h++)
            sm[h] += __shfl_xor_sync(0xffffffffu, sm[h], o);
    if (lane == 0)
#pragma unroll
        for (int h = 0; h < HH; h++) reds_[h][wid] = sm[h];
    __syncthreads();

#pragma unroll
    for (int h = 0; h < HH; h++) {
        float s = reds_[h][0];
#pragma unroll
        for (int i = 1; i < 8; i++) s += reds_[h][i];
        float inv = __frcp_rn(s);
        size_t base = ((size_t)(b * HH + h) * NF + n) * NF;
        A_out[base + tid] = e0[h] * inv;
        if (m1 < NF) A_out[base + m1] = e1[h] * inv;
    }
}

// ---------------------------------------------------------------------------
// K3: out[b,n,d] = 0.25 * sum_h sum_m A[b,h,n,m] * xt[b,m,h,d]
// 32 n-rows per block; col = tid -> (h,d). f32x2 over row pairs, acc[16].
// ---------------------------------------------------------------------------
__global__ void k3_apply(const float* __restrict__ A) {
    int b = blockIdx.y;
    int n0 = blockIdx.x << 5;  // 32 rows
    int tid = threadIdx.x;     // 256
    int h = tid >> 6;

    __shared__ __align__(16) float xts[16 * HD];       // [j][c]
    __shared__ __align__(8) float As[4][16][34];       // [h][j][r], pad 34
    __shared__ float sred[2][256];

    ull acc[16];
#pragma unroll
    for (int i = 0; i < 16; i++) acc[i] = 0ull;

    int r = tid >> 3, jj = tid & 7;

    for (int m0 = 0; m0 < NF; m0 += 16) {
#pragma unroll
        for (int k = 0; k < 4; k++) {
            int f = tid + (k << 8);
            int j = f >> 6, c = (f & 63) << 2;
            int m = m0 + j;
            float4 v = make_float4(0.f, 0.f, 0.f, 0.f);
            if (m < NF)
                v = *reinterpret_cast<const float4*>(g_xt + ((size_t)b * NF + m) * HD + c);
            *reinterpret_cast<float4*>(xts + j * HD + c) = v;
        }
#pragma unroll
        for (int hh = 0; hh < 4; hh++) {
            int n = n0 + r, m = m0 + 2 * jj;
            float2 v = make_float2(0.f, 0.f);
            if (n < NF && m < NF)
                v = *reinterpret_cast<const float2*>(
                        A + ((size_t)(b * HH + hh) * NF + n) * NF + m);
            As[hh][2 * jj][r] = v.x;
            As[hh][2 * jj + 1][r] = v.y;
        }
        __syncthreads();
#pragma unroll
        for (int j = 0; j < 16; j++) {
            float xv = xts[j * HD + tid];
            ull xv2 = pack2(xv, xv);
#pragma unroll
            for (int r2 = 0; r2 < 16; r2++)
                fma2(acc[r2], *reinterpret_cast<const ull*>(&As[h][j][2 * r2]), xv2);
        }
        __syncthreads();
    }

#pragma unroll
    for (int r2 = 0; r2 < 16; r2++) {
        float2 v = unpack2(acc[r2]);
        sred[0][tid] = v.x;
        sred[1][tid] = v.y;
        __syncthreads();
        if (tid < 128) {
            int p = tid >> 6, dd = tid & 63;
            int n = n0 + 2 * r2 + p;
            if (n < NF) {
                float s = sred[p][dd] + sred[p][dd + 64] + sred[p][dd + 128] + sred[p][dd + 192];
                g_out[((size_t)b * NF + n) * DD + dd] = 0.25f * s;
            }
        }
        __syncthreads();
    }
}

// ---------------------------------------------------------------------------
// K4: g = out @ fcg_w + fcg_b; GLU; residual; LayerNorm.
// 8 rows/block; fcg_w staged in smem; f32x2 row pairs; warp-per-row LN.
// ---------------------------------------------------------------------------
__global__ void k4_glu_ln(const float* __restrict__ x,
                          const float* __restrict__ fw, const float* __restrict__ fb,
                          const float* __restrict__ lgm, const float* __restrict__ lbt,
                          float* __restrict__ y) {
    int bn0 = blockIdx.x << 3;
    int tid = threadIdx.x;  // 256
    __shared__ __align__(16) float fws[DD * 128];   // 32 KB
    __shared__ __align__(8) float orowT[DD][10];    // [d][row], pad 10
    __shared__ float gsh[8][128];

#pragma unroll
    for (int k = 0; k < 8; k++) {
        int f = (tid + (k << 8)) << 2;
        *reinterpret_cast<float4*>(fws + f) = *reinterpret_cast<const float4*>(fw + f);
    }
#pragma unroll
    for (int k = 0; k < 2; k++) {
        int i = tid + (k << 8);
        int rr = i >> 6, d = i & 63;
        orowT[d][rr] = g_out[(size_t)(bn0 + rr) * DD + d];
    }
    __syncthreads();

    int col = tid & 127, rh = tid >> 7;
    float fbv = fb[col];
    ull acc01 = pack2(fbv, fbv);
    ull acc23 = pack2(fbv, fbv);
#pragma unroll
    for (int d = 0; d < DD; d++) {
        float fv = fws[d * 128 + col];
        ull fv2 = pack2(fv, fv);
        ull o01 = *reinterpret_cast<const ull*>(&orowT[d][rh * 4]);
        ull o23 = *reinterpret_cast<const ull*>(&orowT[d][rh * 4 + 2]);
        fma2(acc01, o01, fv2);
        fma2(acc23, o23, fv2);
    }
    {
        float2 v01 = unpack2(acc01);
        float2 v23 = unpack2(acc23);
        gsh[rh * 4 + 0][col] = v01.x;
        gsh[rh * 4 + 1][col] = v01.y;
        gsh[rh * 4 + 2][col] = v23.x;
        gsh[rh * 4 + 3][col] = v23.y;
    }
    __syncthreads();

    int w = tid >> 5, l = tid & 31;
    int bn = bn0 + w;
    float yv0, yv1;
    {
        float a0 = gsh[w][l],      b0 = gsh[w][l + 64];
        float a1 = gsh[w][l + 32], b1 = gsh[w][l + 96];
        float s0 = 1.f / (1.f + __expf(-b0));
        float s1 = 1.f / (1.f + __expf(-b1));
        yv0 = fmaf(a0, s0, x[(size_t)bn * DD + l]);
        yv1 = fmaf(a1, s1, x[(size_t)bn * DD + l + 32]);
    }
    float s = yv0 + yv1;
#pragma unroll
    for (int o = 16; o; o >>= 1) s += __shfl_xor_sync(0xffffffffu, s, o);
    float mu = s * (1.f / 64.f);
    float d0 = yv0 - mu, d1 = yv1 - mu;
    float q = d0 * d0 + d1 * d1;
#pragma unroll
    for (int o = 16; o; o >>= 1) q += __shfl_xor_sync(0xffffffffu, q, o);
    float rs = rsqrtf(q * (1.f / 64.f) + 1e-5f);
    y[(size_t)bn * DD + l]      = d0 * rs * lgm[l]      + lbt[l];
    y[(size_t)bn * DD + l + 32] = d1 * rs * lgm[l + 32] + lbt[l + 32];
}

// ---------------------------------------------------------------------------
extern "C" void kernel_launch(void* const* d_in, const int* in_sizes, int n_in,
                              void* d_out, int out_size) {
    const float* x      = (const float*)d_in[0];
    const float* causal = (const float*)d_in[1];
    const float* W      = (const float*)d_in[2];
    const float* attw   = (const float*)d_in[3];
    const float* conv_w = (const float*)d_in[4];
    const float* conv_b = (const float*)d_in[5];
    const float* fcg_w  = (const float*)d_in[6];
    const float* fcg_b  = (const float*)d_in[7];
    const float* ln_g   = (const float*)d_in[8];
    const float* ln_b   = (const float*)d_in[9];

    float* y = (float*)d_out;
    float* A = (float*)d_out + (size_t)BB * NF * DD;   // (y, A) flattened in order

    k1_proj<<<(BB * NF) / 8, 256>>>(x, W, attw);
    k2a_cconv<<<NF, 256>>>(causal, conv_w, conv_b);
    k2_attn<<<dim3(NF, BB), 256>>>(conv_w, A);
    k3_apply<<<dim3((NF + 31) / 32, BB), 256>>>(A);
    k4_glu_ln<<<(BB * NF) / 8, 256>>>(x, fcg_w, fcg_b, ln_g, ln_b, y);
}

// round 5
// speedup vs baseline: 1.2964x; 1.0933x over previous
#include <cuda_runtime.h>

#define NF 510
#define BB 32
#define DD 64
#define HH 4
#define HD 256   // H*D

typedef unsigned long long ull;

// Scratch (static device arrays are the sanctioned workaround)
__device__ float g_xt[(size_t)BB * NF * HD];        // (b, n, h*64+d)
__device__ float g_si[BB * HH * NF];
__device__ float g_sj[BB * HH * NF];
__device__ float g_out[(size_t)BB * NF * DD];
__device__ float g_cconv[(size_t)HH * NF * NF];     // conv(causal)+bias, b-independent
__device__ float g_amean[(size_t)BB * NF * 512];    // A_eva mean over heads, stride 512

__device__ __forceinline__ ull pack2(float a, float b) {
    ull r; asm("mov.b64 %0, {%1, %2};" : "=l"(r) : "f"(a), "f"(b)); return r;
}
__device__ __forceinline__ void fma2(ull& acc, ull a, ull b) {
    asm("fma.rn.f32x2 %0, %1, %2, %0;" : "+l"(acc) : "l"(a), "l"(b));
}
__device__ __forceinline__ float2 unpack2(ull v) {
    float2 f; asm("mov.b64 {%0, %1}, %2;" : "=f"(f.x), "=f"(f.y) : "l"(v)); return f;
}

// ---------------------------------------------------------------------------
// K1: xt = x @ W  (+ s_i, s_j head scores). 8 rows/block, f32x2 row pairs.
// ---------------------------------------------------------------------------
__global__ void k1_proj(const float* __restrict__ x, const float* __restrict__ W,
                        const float* __restrict__ attw) {
    int bn0 = blockIdx.x << 3;
    int tid = threadIdx.x;              // 256, col = tid
    __shared__ __align__(8) float xs[DD][10];
    __shared__ float red[8][8][2];

#pragma unroll
    for (int k = 0; k < 2; k++) {
        int i = tid + (k << 8);
        int r = i >> 6, d = i & 63;
        xs[d][r] = x[(size_t)(bn0 + r) * DD + d];
    }
    __syncthreads();

    ull acc[4] = {0ull, 0ull, 0ull, 0ull};
#pragma unroll
    for (int d = 0; d < DD; d++) {
        float wv = W[d * HD + tid];
        ull wv2 = pack2(wv, wv);
#pragma unroll
        for (int p = 0; p < 4; p++) {
            ull xp = *reinterpret_cast<const ull*>(&xs[d][2 * p]);
            fma2(acc[p], xp, wv2);
        }
    }
    float accs[8];
#pragma unroll
    for (int p = 0; p < 4; p++) {
        float2 v = unpack2(acc[p]);
        accs[2 * p] = v.x; accs[2 * p + 1] = v.y;
    }
#pragma unroll
    for (int r = 0; r < 8; r++)
        g_xt[(size_t)(bn0 + r) * HD + tid] = accs[r];

    int h = tid >> 6, dd = tid & 63;
    float w1 = attw[h * 128 + dd];
    float w2 = attw[h * 128 + 64 + dd];
    int wid = tid >> 5, lane = tid & 31;
#pragma unroll
    for (int r = 0; r < 8; r++) {
        float v1 = accs[r] * w1;
        float v2 = accs[r] * w2;
#pragma unroll
        for (int o = 16; o; o >>= 1) {
            v1 += __shfl_xor_sync(0xffffffffu, v1, o);
            v2 += __shfl_xor_sync(0xffffffffu, v2, o);
        }
        if (lane == 0) { red[r][wid][0] = v1; red[r][wid][1] = v2; }
    }
    __syncthreads();
    if (tid < 32) {
        int r = tid >> 2, hh = tid & 3;
        int bn = bn0 + r;
        int b = bn / NF, n = bn - b * NF;
        g_si[(b * HH + hh) * NF + n] = red[r][2 * hh][0] + red[r][2 * hh + 1][0];
        g_sj[(b * HH + hh) * NF + n] = red[r][2 * hh][1] + red[r][2 * hh + 1][1];
    }
}

// ---------------------------------------------------------------------------
// K2a: causal-channel conv + bias, b-independent, once per (h,n,m).
// ---------------------------------------------------------------------------
__global__ void k2a_cconv(const float* __restrict__ causal,
                          const float* __restrict__ conv_w,
                          const float* __restrict__ conv_b) {
    int n = blockIdx.x;
    int tid = threadIdx.x;  // 256
    __shared__ float caus[3][512];
    __shared__ float cw[72];
    __shared__ float cb[4];

    if (tid < 72) cw[tid] = conv_w[tid];
    if (tid >= 96 && tid < 100) cb[tid - 96] = conv_b[tid - 96];
    for (int i = tid; i < 3 * 512; i += 256) {
        int rr = i >> 9, mm = i & 511;
        int r = n - 1 + rr, m = mm - 1;
        caus[rr][mm] = (r >= 0 && r < NF && m >= 0 && m < NF) ? causal[r * NF + m] : 0.f;
    }
    __syncthreads();

#pragma unroll
    for (int s = 0; s < 2; s++) {
        int m = tid + (s << 8);
        if (m < NF) {
#pragma unroll
            for (int h = 0; h < HH; h++) {
                float st = cb[h];
#pragma unroll
                for (int rr = 0; rr < 3; rr++)
#pragma unroll
                    for (int dj = 0; dj < 3; dj++)
                        st = fmaf(cw[((h * 2 + 1) * 3 + rr) * 3 + dj], caus[rr][m + dj], st);
                g_cconv[((size_t)h * NF + n) * NF + m] = st;
            }
        }
    }
}

// ---------------------------------------------------------------------------
// K2b: amean[b,n,m] = 0.25 * sum_h leaky(si[h,n] + sj[h,m]), once per element.
// ---------------------------------------------------------------------------
__global__ void k2b_amean() {
    int n = blockIdx.x, b = blockIdx.y;
    int tid = threadIdx.x;  // 256
    __shared__ float sjs[HH][512];
    __shared__ float sic[HH];

    if (tid < HH) sic[tid] = g_si[(b * HH + tid) * NF + n];
    for (int i = tid; i < HH * 512; i += 256) {
        int h = i >> 9, m = i & 511;
        sjs[h][m] = (m < NF) ? g_sj[(b * HH + h) * NF + m] : 0.f;
    }
    __syncthreads();

#pragma unroll
    for (int s = 0; s < 2; s++) {
        int m = tid + (s << 8);
        float a = 0.f;
#pragma unroll
        for (int h = 0; h < HH; h++) {
            float e = sic[h] + sjs[h][m];
            a += (e >= 0.f) ? e : 0.01f * e;
        }
        g_amean[((size_t)b * NF + n) * 512 + m] = 0.25f * a;
    }
}

// ---------------------------------------------------------------------------
// K2: per (b,n): load 3 amean rows + cconv row, conv, logits, softmax, write A.
// ---------------------------------------------------------------------------
__global__ void k2_attn(const float* __restrict__ conv_w,
                        float* __restrict__ A_out) {
    int n = blockIdx.x, b = blockIdx.y;
    int tid = threadIdx.x;  // 256
    int wid = tid >> 5, lane = tid & 31;

    __shared__ float am3[3][512];   // index mm = m+1
    __shared__ float sjs[HH][512];
    __shared__ float cw0[36];
    __shared__ float si1[HH];
    __shared__ float redm[HH][8];
    __shared__ float reds_[HH][8];

    if (tid < 36) {
        int h = tid / 9, k = tid - h * 9;
        cw0[tid] = conv_w[h * 18 + k];   // amean channel
    }
    if (tid >= 40 && tid < 44) si1[tid - 40] = g_si[(b * HH + (tid - 40)) * NF + n];
    for (int i = tid; i < HH * 512; i += 256) {
        int h = i >> 9, m = i & 511;
        sjs[h][m] = (m < NF) ? g_sj[(b * HH + h) * NF + m] : 0.f;
    }
    for (int i = tid; i < 3 * 512; i += 256) {
        int rr = i >> 9, mm = i & 511;
        int r = n - 1 + rr, m = mm - 1;
        am3[rr][mm] = (r >= 0 && r < NF && m >= 0 && m < NF)
                          ? g_amean[((size_t)b * NF + r) * 512 + m] : 0.f;
    }
    __syncthreads();

    float lg[2][HH];
#pragma unroll
    for (int s = 0; s < 2; s++) {
        int m = tid + (s << 8);
        if (m < NF) {
            float av[3][3];
#pragma unroll
            for (int rr = 0; rr < 3; rr++)
#pragma unroll
                for (int dj = 0; dj < 3; dj++)
                    av[rr][dj] = am3[rr][m + dj];
#pragma unroll
            for (int h = 0; h < HH; h++) {
                float st = g_cconv[((size_t)h * NF + n) * NF + m];
#pragma unroll
                for (int rr = 0; rr < 3; rr++)
#pragma unroll
                    for (int dj = 0; dj < 3; dj++)
                        st = fmaf(cw0[h * 9 + rr * 3 + dj], av[rr][dj], st);
                float e = si1[h] + sjs[h][m];
                float aeva = (e >= 0.f) ? e : 0.01f * e;
                lg[s][h] = fmaf(0.1f, aeva, 0.9f * st);
            }
        } else {
#pragma unroll
            for (int h = 0; h < HH; h++) lg[s][h] = -1e30f;
        }
    }

    float mx[HH];
#pragma unroll
    for (int h = 0; h < HH; h++) mx[h] = fmaxf(lg[0][h], lg[1][h]);
#pragma unroll
    for (int o = 16; o; o >>= 1)
#pragma unroll
        for (int h = 0; h < HH; h++)
            mx[h] = fmaxf(mx[h], __shfl_xor_sync(0xffffffffu, mx[h], o));
    if (lane == 0)
#pragma unroll
        for (int h = 0; h < HH; h++) redm[h][wid] = mx[h];
    __syncthreads();

    float e0[HH], e1[HH], sm[HH];
    int m1 = tid + 256;
#pragma unroll
    for (int h = 0; h < HH; h++) {
        float g = redm[h][0];
#pragma unroll
        for (int i = 1; i < 8; i++) g = fmaxf(g, redm[h][i]);
        e0[h] = __expf(lg[0][h] - g);
        e1[h] = (m1 < NF) ? __expf(lg[1][h] - g) : 0.f;
        sm[h] = e0[h] + e1[h];
    }
#pragma unroll
    for (int o = 16; o; o >>= 1)
#pragma unroll
        for (int h = 0; h < HH; h++)
            sm[h] += __shfl_xor_sync(0xffffffffu, sm[h], o);
    if (lane == 0)
#pragma unroll
        for (int h = 0; h < HH; h++) reds_[h][wid] = sm[h];
    __syncthreads();

#pragma unroll
    for (int h = 0; h < HH; h++) {
        float s = reds_[h][0];
#pragma unroll
        for (int i = 1; i < 8; i++) s += reds_[h][i];
        float inv = __frcp_rn(s);
        size_t base = ((size_t)(b * HH + h) * NF + n) * NF;
        A_out[base + tid] = e0[h] * inv;
        if (m1 < NF) A_out[base + m1] = e1[h] * inv;
    }
}

// ---------------------------------------------------------------------------
// K3: out[b,n,d] = 0.25 * sum_h sum_m A[b,h,n,m] * xt[b,m,h,d]
// 64-row blocks. Thread tile: 16 row-pairs x 2 cols. A row-pair LDS.64 is a
// warp-uniform broadcast reused across 2 cols. cp.async double-buffered xt,
// register-prefetched A staging.
// Dynamic smem layout (floats): [0,4096) xts0 | [4096,8192) xts1 |
//   [8192,12416) As0 (4*16*66) | [12416,16640) As1. Epilogue reuses [0,16384).
// ---------------------------------------------------------------------------
__global__ __launch_bounds__(256, 2) void k3_apply(const float* __restrict__ A) {
    extern __shared__ __align__(16) float sb[];
    int b = blockIdx.y;
    int n0 = blockIdx.x << 6;     // 64 rows
    int tid = threadIdx.x;        // 256
    int cp = tid & 127, rg = tid >> 7, h = cp >> 5;
    unsigned sbase = (unsigned)__cvta_generic_to_shared(sb);

    ull acc[16][2];
#pragma unroll
    for (int p = 0; p < 16; p++) { acc[p][0] = 0ull; acc[p][1] = 0ull; }

    float2 aF[8];

    // ---- prologue: A-regs tile 0, cp.async xt tile 0 -> buf0
#pragma unroll
    for (int k = 0; k < 8; k++) {
        int u = tid + (k << 8);
        int hh = u >> 9, rem = u & 511, r = rem >> 3, ch = rem & 7;
        int nn = n0 + r, m = ch * 2;
        float2 v = make_float2(0.f, 0.f);
        if (nn < NF && m < NF)
            v = *reinterpret_cast<const float2*>(A + ((size_t)(b * HH + hh) * NF + nn) * NF + m);
        aF[k] = v;
    }
#pragma unroll
    for (int k = 0; k < 4; k++) {
        int q = tid + (k << 8);
        int j = q >> 6, cg = (q & 63) << 2;
        int m = j;  // m0 = 0
        const float* src = g_xt + ((size_t)b * NF + m) * HD + cg;
        asm volatile("cp.async.cg.shared.global [%0], [%1], 16, %2;"
                     :: "r"(sbase + (unsigned)(j * 256 + cg) * 4u), "l"(src), "r"(16));
    }
    asm volatile("cp.async.commit_group;" ::: "memory");

    for (int t = 0; t < 32; t++) {
        int cur = t & 1;
        asm volatile("cp.async.wait_group 0;" ::: "memory");

        // STS A regs -> As[cur]
        {
            float* Asb = sb + 8192 + cur * 4224;
#pragma unroll
            for (int k = 0; k < 8; k++) {
                int u = tid + (k << 8);
                int hh = u >> 9, rem = u & 511, r = rem >> 3, ch = rem & 7;
                float* dst = Asb + (hh * 16 + ch * 2) * 66 + r;
                dst[0] = aF[k].x;
                dst[66] = aF[k].y;
            }
        }
        __syncthreads();

        if (t < 31) {
            int m0n = (t + 1) << 4;
            unsigned xd = sbase + (unsigned)((cur ^ 1) * 4096) * 4u;
#pragma unroll
            for (int k = 0; k < 4; k++) {
                int q = tid + (k << 8);
                int j = q >> 6, cg = (q & 63) << 2;
                int m = m0n + j;
                int mc = (m < NF) ? m : 0;
                const float* src = g_xt + ((size_t)b * NF + mc) * HD + cg;
                int sz = (m < NF) ? 16 : 0;
                asm volatile("cp.async.cg.shared.global [%0], [%1], 16, %2;"
                             :: "r"(xd + (unsigned)(j * 256 + cg) * 4u), "l"(src), "r"(sz));
            }
            asm volatile("cp.async.commit_group;" ::: "memory");
#pragma unroll
            for (int k = 0; k < 8; k++) {
                int u = tid + (k << 8);
                int hh = u >> 9, rem = u & 511, r = rem >> 3, ch = rem & 7;
                int nn = n0 + r, m = m0n + ch * 2;
                float2 v = make_float2(0.f, 0.f);
                if (nn < NF && m < NF)
                    v = *reinterpret_cast<const float2*>(A + ((size_t)(b * HH + hh) * NF + nn) * NF + m);
                aF[k] = v;
            }
        }

        // compute on buf cur
        {
            const float* xb = sb + cur * 4096;
            const float* Ab = sb + 8192 + cur * 4224 + (h * 16) * 66 + rg * 32;
#pragma unroll 4
            for (int j = 0; j < 16; j++) {
                float2 xv = *reinterpret_cast<const float2*>(xb + j * 256 + 2 * cp);
                ull x0 = pack2(xv.x, xv.x);
                ull x1 = pack2(xv.y, xv.y);
                const float* Ar = Ab + j * 66;
#pragma unroll
                for (int p = 0; p < 16; p++) {
                    ull a2 = *reinterpret_cast<const ull*>(Ar + 2 * p);
                    fma2(acc[p][0], a2, x0);
                    fma2(acc[p][1], a2, x1);
                }
            }
        }
    }
    __syncthreads();

    // epilogue: partials -> smem, reduce over h, store
#pragma unroll
    for (int p = 0; p < 16; p++) {
        int row = rg * 32 + 2 * p;
        float2 a0 = unpack2(acc[p][0]);   // (row, c0), (row+1, c0)
        float2 a1 = unpack2(acc[p][1]);   // (row, c1), (row+1, c1)
        *reinterpret_cast<float2*>(sb + row * 256 + 2 * cp) = make_float2(a0.x, a1.x);
        *reinterpret_cast<float2*>(sb + (row + 1) * 256 + 2 * cp) = make_float2(a0.y, a1.y);
    }
    __syncthreads();
#pragma unroll
    for (int k = 0; k < 16; k++) {
        int o = tid + (k << 8);
        int r = o >> 6, d = o & 63;
        int nn = n0 + r;
        if (nn < NF) {
            float s = sb[r * 256 + d] + sb[r * 256 + d + 64] +
                      sb[r * 256 + d + 128] + sb[r * 256 + d + 192];
            g_out[((size_t)b * NF + nn) * DD + d] = 0.25f * s;
        }
    }
}

// ---------------------------------------------------------------------------
// K4: g = out @ fcg_w + fcg_b; GLU; residual; LayerNorm. 8 rows/block.
// ---------------------------------------------------------------------------
__global__ void k4_glu_ln(const float* __restrict__ x,
                          const float* __restrict__ fw, const float* __restrict__ fb,
                          const float* __restrict__ lgm, const float* __restrict__ lbt,
                          float* __restrict__ y) {
    int bn0 = blockIdx.x << 3;
    int tid = threadIdx.x;  // 256
    __shared__ __align__(16) float fws[DD * 128];
    __shared__ __align__(8) float orowT[DD][10];
    __shared__ float gsh[8][128];

#pragma unroll
    for (int k = 0; k < 8; k++) {
        int f = (tid + (k << 8)) << 2;
        *reinterpret_cast<float4*>(fws + f) = *reinterpret_cast<const float4*>(fw + f);
    }
#pragma unroll
    for (int k = 0; k < 2; k++) {
        int i = tid + (k << 8);
        int rr = i >> 6, d = i & 63;
        orowT[d][rr] = g_out[(size_t)(bn0 + rr) * DD + d];
    }
    __syncthreads();

    int col = tid & 127, rh = tid >> 7;
    float fbv = fb[col];
    ull acc01 = pack2(fbv, fbv);
    ull acc23 = pack2(fbv, fbv);
#pragma unroll
    for (int d = 0; d < DD; d++) {
        float fv = fws[d * 128 + col];
        ull fv2 = pack2(fv, fv);
        ull o01 = *reinterpret_cast<const ull*>(&orowT[d][rh * 4]);
        ull o23 = *reinterpret_cast<const ull*>(&orowT[d][rh * 4 + 2]);
        fma2(acc01, o01, fv2);
        fma2(acc23, o23, fv2);
    }
    {
        float2 v01 = unpack2(acc01);
        float2 v23 = unpack2(acc23);
        gsh[rh * 4 + 0][col] = v01.x;
        gsh[rh * 4 + 1][col] = v01.y;
        gsh[rh * 4 + 2][col] = v23.x;
        gsh[rh * 4 + 3][col] = v23.y;
    }
    __syncthreads();

    int w = tid >> 5, l = tid & 31;
    int bn = bn0 + w;
    float yv0, yv1;
    {
        float a0 = gsh[w][l],      b0 = gsh[w][l + 64];
        float a1 = gsh[w][l + 32], b1 = gsh[w][l + 96];
        float s0 = 1.f / (1.f + __expf(-b0));
        float s1 = 1.f / (1.f + __expf(-b1));
        yv0 = fmaf(a0, s0, x[(size_t)bn * DD + l]);
        yv1 = fmaf(a1, s1, x[(size_t)bn * DD + l + 32]);
    }
    float s = yv0 + yv1;
#pragma unroll
    for (int o = 16; o; o >>= 1) s += __shfl_xor_sync(0xffffffffu, s, o);
    float mu = s * (1.f / 64.f);
    float d0 = yv0 - mu, d1 = yv1 - mu;
    float q = d0 * d0 + d1 * d1;
#pragma unroll
    for (int o = 16; o; o >>= 1) q += __shfl_xor_sync(0xffffffffu, q, o);
    float rs = rsqrtf(q * (1.f / 64.f) + 1e-5f);
    y[(size_t)bn * DD + l]      = d0 * rs * lgm[l]      + lbt[l];
    y[(size_t)bn * DD + l + 32] = d1 * rs * lgm[l + 32] + lbt[l + 32];
}

// ---------------------------------------------------------------------------
extern "C" void kernel_launch(void* const* d_in, const int* in_sizes, int n_in,
                              void* d_out, int out_size) {
    const float* x      = (const float*)d_in[0];
    const float* causal = (const float*)d_in[1];
    const float* W      = (const float*)d_in[2];
    const float* attw   = (const float*)d_in[3];
    const float* conv_w = (const float*)d_in[4];
    const float* conv_b = (const float*)d_in[5];
    const float* fcg_w  = (const float*)d_in[6];
    const float* fcg_b  = (const float*)d_in[7];
    const float* ln_g   = (const float*)d_in[8];
    const float* ln_b   = (const float*)d_in[9];

    float* y = (float*)d_out;
    float* A = (float*)d_out + (size_t)BB * NF * DD;   // (y, A) flattened in order

    cudaFuncSetAttribute(k3_apply, cudaFuncAttributeMaxDynamicSharedMemorySize, 66560);

    k1_proj<<<(BB * NF) / 8, 256>>>(x, W, attw);
    k2a_cconv<<<NF, 256>>>(causal, conv_w, conv_b);
    k2b_amean<<<dim3(NF, BB), 256>>>();
    k2_attn<<<dim3(NF, BB), 256>>>(conv_w, A);
    k3_apply<<<dim3(8, BB), 256, 66560>>>(A);
    k4_glu_ln<<<(BB * NF) / 8, 256>>>(x, fcg_w, fcg_b, ln_g, ln_b, y);
}

// round 6
// speedup vs baseline: 1.7402x; 1.3424x over previous
#include <cuda_runtime.h>

#define NF 510
#define BB 32
#define DD 64
#define HH 4
#define HD 256   // H*D

typedef unsigned long long ull;

// Scratch (static device arrays are the sanctioned workaround)
__device__ float g_xt[(size_t)BB * NF * HD];        // (b, n, h*64+d)
__device__ float g_si[BB * HH * NF];
__device__ float g_sj[BB * HH * NF];
__device__ float g_out[(size_t)BB * NF * DD];
__device__ float g_cconv[(size_t)HH * NF * NF];     // 0.9*(conv(causal)+bias), b-independent

__device__ __forceinline__ ull pack2(float a, float b) {
    ull r; asm("mov.b64 %0, {%1, %2};" : "=l"(r) : "f"(a), "f"(b)); return r;
}
__device__ __forceinline__ void fma2(ull& acc, ull a, ull b) {
    asm("fma.rn.f32x2 %0, %1, %2, %0;" : "+l"(acc) : "l"(a), "l"(b));
}
__device__ __forceinline__ float2 unpack2(ull v) {
    float2 f; asm("mov.b64 {%0, %1}, %2;" : "=f"(f.x), "=f"(f.y) : "l"(v)); return f;
}

// ---------------------------------------------------------------------------
// K1: xt = x @ W  (+ s_i, s_j head scores). 8 rows/block, f32x2 row pairs.
// ---------------------------------------------------------------------------
__global__ void k1_proj(const float* __restrict__ x, const float* __restrict__ W,
                        const float* __restrict__ attw) {
    int bn0 = blockIdx.x << 3;
    int tid = threadIdx.x;              // 256, col = tid
    __shared__ __align__(8) float xs[DD][10];
    __shared__ float red[8][8][2];

#pragma unroll
    for (int k = 0; k < 2; k++) {
        int i = tid + (k << 8);
        int r = i >> 6, d = i & 63;
        xs[d][r] = x[(size_t)(bn0 + r) * DD + d];
    }
    __syncthreads();

    ull acc[4] = {0ull, 0ull, 0ull, 0ull};
#pragma unroll
    for (int d = 0; d < DD; d++) {
        float wv = W[d * HD + tid];
        ull wv2 = pack2(wv, wv);
#pragma unroll
        for (int p = 0; p < 4; p++) {
            ull xp = *reinterpret_cast<const ull*>(&xs[d][2 * p]);
            fma2(acc[p], xp, wv2);
        }
    }
    float accs[8];
#pragma unroll
    for (int p = 0; p < 4; p++) {
        float2 v = unpack2(acc[p]);
        accs[2 * p] = v.x; accs[2 * p + 1] = v.y;
    }
#pragma unroll
    for (int r = 0; r < 8; r++)
        g_xt[(size_t)(bn0 + r) * HD + tid] = accs[r];

    int h = tid >> 6, dd = tid & 63;
    float w1 = attw[h * 128 + dd];
    float w2 = attw[h * 128 + 64 + dd];
    int wid = tid >> 5, lane = tid & 31;
#pragma unroll
    for (int r = 0; r < 8; r++) {
        float v1 = accs[r] * w1;
        float v2 = accs[r] * w2;
#pragma unroll
        for (int o = 16; o; o >>= 1) {
            v1 += __shfl_xor_sync(0xffffffffu, v1, o);
            v2 += __shfl_xor_sync(0xffffffffu, v2, o);
        }
        if (lane == 0) { red[r][wid][0] = v1; red[r][wid][1] = v2; }
    }
    __syncthreads();
    if (tid < 32) {
        int r = tid >> 2, hh = tid & 3;
        int bn = bn0 + r;
        int b = bn / NF, n = bn - b * NF;
        g_si[(b * HH + hh) * NF + n] = red[r][2 * hh][0] + red[r][2 * hh + 1][0];
        g_sj[(b * HH + hh) * NF + n] = red[r][2 * hh][1] + red[r][2 * hh + 1][1];
    }
}

// ---------------------------------------------------------------------------
// K2a: 0.9 * (causal-channel conv + bias), b-independent, once per (h,n,m).
// ---------------------------------------------------------------------------
__global__ void k2a_cconv(const float* __restrict__ causal,
                          const float* __restrict__ conv_w,
                          const float* __restrict__ conv_b) {
    int n = blockIdx.x;
    int tid = threadIdx.x;  // 256
    __shared__ float caus[3][512];
    __shared__ float cw[72];
    __shared__ float cb[4];

    if (tid < 72) cw[tid] = conv_w[tid];
    if (tid >= 96 && tid < 100) cb[tid - 96] = conv_b[tid - 96];
    for (int i = tid; i < 3 * 512; i += 256) {
        int rr = i >> 9, mm = i & 511;
        int r = n - 1 + rr, m = mm - 1;
        caus[rr][mm] = (r >= 0 && r < NF && m >= 0 && m < NF) ? causal[r * NF + m] : 0.f;
    }
    __syncthreads();

#pragma unroll
    for (int s = 0; s < 2; s++) {
        int m = tid + (s << 8);
        if (m < NF) {
#pragma unroll
            for (int h = 0; h < HH; h++) {
                float st = cb[h];
#pragma unroll
                for (int rr = 0; rr < 3; rr++)
#pragma unroll
                    for (int dj = 0; dj < 3; dj++)
                        st = fmaf(cw[((h * 2 + 1) * 3 + rr) * 3 + dj], caus[rr][m + dj], st);
                g_cconv[((size_t)h * NF + n) * NF + m] = 0.9f * st;
            }
        }
    }
}

// ---------------------------------------------------------------------------
// K2: 8 n-rows per block, one warp per row. amean rows n0-1..n0+8 computed
// in smem from si/sj. Per warp: head-pairs, logits in registers, warp-level
// softmax (no block barriers in the main loop). Writes A.
// ---------------------------------------------------------------------------
__global__ __launch_bounds__(256) void k2_attn(const float* __restrict__ conv_w,
                                               float* __restrict__ A_out) {
    int b = blockIdx.y;
    int n0 = blockIdx.x << 3;
    int tid = threadIdx.x;  // 256
    int wid = tid >> 5, lane = tid & 31;

    __shared__ float sjs[HH][512];
    __shared__ float am[10][512];     // rows n0-1 .. n0+8; col mm = m+1... no: col = m directly? see below
    __shared__ float cw9[HH][9];      // 0.9 * amean-channel conv weights
    __shared__ float si_blk[10][HH];  // si rows n0-1 .. n0+8

    if (tid < 36) {
        int h = tid / 9, k = tid - h * 9;
        cw9[h][k] = 0.9f * conv_w[h * 18 + k];
    }
    if (tid >= 64 && tid < 104) {
        int t = tid - 64, rr = t >> 2, h = t & 3;
        int r = n0 - 1 + rr;
        si_blk[rr][h] = (r >= 0 && r < NF) ? g_si[(b * HH + h) * NF + r] : 0.f;
    }
    for (int i = tid; i < HH * 512; i += 256) {
        int h = i >> 9, m = i & 511;
        sjs[h][m] = (m < NF) ? g_sj[(b * HH + h) * NF + m] : 0.f;
    }
    __syncthreads();

    // amean rows: am[rr][mm], mm = m+1 (mm 0 and 511 are zero pads)
    for (int i = tid; i < 10 * 512; i += 256) {
        int rr = i / 512, mm = i - rr * 512;
        int r = n0 - 1 + rr, m = mm - 1;
        float a = 0.f;
        if (r >= 0 && r < NF && m >= 0 && m < NF) {
#pragma unroll
            for (int h = 0; h < HH; h++) {
                float e = si_blk[rr][h] + sjs[h][m];
                a += (e >= 0.f) ? e : 0.01f * e;
            }
            a *= 0.25f;
        }
        am[rr][mm] = a;
    }
    __syncthreads();

    int n = n0 + wid;
    bool active = n < NF;
    float si1[HH];
#pragma unroll
    for (int h = 0; h < HH; h++) si1[h] = si_blk[wid + 1][h];

#pragma unroll
    for (int hp = 0; hp < 2; hp++) {
        int h0 = hp << 1, h1 = h0 + 1;
        const float* cc0 = g_cconv + ((size_t)h0 * NF + n) * NF;
        const float* cc1 = g_cconv + ((size_t)h1 * NF + n) * NF;
        float lg0[16], lg1[16];
        float mx0 = -1e30f, mx1 = -1e30f;

#pragma unroll
        for (int c = 0; c < 16; c++) {
            int m = (c << 5) + lane;
            float l0 = -1e30f, l1 = -1e30f;
            if (active && m < NF) {
                // conv taps at am[wid + rr][m + dj]  (mm = m+1 -> taps m..m+2)
                float st0 = cc0[m];
                float st1 = cc1[m];
#pragma unroll
                for (int rr = 0; rr < 3; rr++) {
                    float a0 = am[wid + rr][m];
                    float a1 = am[wid + rr][m + 1];
                    float a2 = am[wid + rr][m + 2];
                    st0 = fmaf(cw9[h0][rr * 3 + 0], a0, st0);
                    st0 = fmaf(cw9[h0][rr * 3 + 1], a1, st0);
                    st0 = fmaf(cw9[h0][rr * 3 + 2], a2, st0);
                    st1 = fmaf(cw9[h1][rr * 3 + 0], a0, st1);
                    st1 = fmaf(cw9[h1][rr * 3 + 1], a1, st1);
                    st1 = fmaf(cw9[h1][rr * 3 + 2], a2, st1);
                }
                float e0 = si1[h0] + sjs[h0][m];
                float e1 = si1[h1] + sjs[h1][m];
                float av0 = (e0 >= 0.f) ? e0 : 0.01f * e0;
                float av1 = (e1 >= 0.f) ? e1 : 0.01f * e1;
                l0 = fmaf(0.1f, av0, st0);
                l1 = fmaf(0.1f, av1, st1);
            }
            lg0[c] = l0; lg1[c] = l1;
            mx0 = fmaxf(mx0, l0); mx1 = fmaxf(mx1, l1);
        }

#pragma unroll
        for (int o = 16; o; o >>= 1) {
            mx0 = fmaxf(mx0, __shfl_xor_sync(0xffffffffu, mx0, o));
            mx1 = fmaxf(mx1, __shfl_xor_sync(0xffffffffu, mx1, o));
        }
        float s0 = 0.f, s1 = 0.f;
#pragma unroll
        for (int c = 0; c < 16; c++) {
            float e0 = __expf(lg0[c] - mx0);
            float e1 = __expf(lg1[c] - mx1);
            lg0[c] = e0; lg1[c] = e1;
            s0 += e0; s1 += e1;
        }
#pragma unroll
        for (int o = 16; o; o >>= 1) {
            s0 += __shfl_xor_sync(0xffffffffu, s0, o);
            s1 += __shfl_xor_sync(0xffffffffu, s1, o);
        }
        float inv0 = __frcp_rn(s0);
        float inv1 = __frcp_rn(s1);

        if (active) {
            float* d0 = A_out + ((size_t)(b * HH + h0) * NF + n) * NF;
            float* d1 = A_out + ((size_t)(b * HH + h1) * NF + n) * NF;
#pragma unroll
            for (int c = 0; c < 16; c++) {
                int m = (c << 5) + lane;
                if (m < NF) {
                    d0[m] = lg0[c] * inv0;
                    d1[m] = lg1[c] * inv1;
                }
            }
        }
    }
}

// ---------------------------------------------------------------------------
// K3: out[b,n,d] = 0.25 * sum_h sum_m A[b,h,n,m] * xt[b,m,h,d]
// 64-row blocks, 16 row-pairs x 2 cols per thread, cp.async double-buffered.
// ---------------------------------------------------------------------------
__global__ __launch_bounds__(256, 2) void k3_apply(const float* __restrict__ A) {
    extern __shared__ __align__(16) float sb[];
    int b = blockIdx.y;
    int n0 = blockIdx.x << 6;     // 64 rows
    int tid = threadIdx.x;        // 256
    int cp = tid & 127, rg = tid >> 7, h = cp >> 5;
    unsigned sbase = (unsigned)__cvta_generic_to_shared(sb);

    ull acc[16][2];
#pragma unroll
    for (int p = 0; p < 16; p++) { acc[p][0] = 0ull; acc[p][1] = 0ull; }

    float2 aF[8];

#pragma unroll
    for (int k = 0; k < 8; k++) {
        int u = tid + (k << 8);
        int hh = u >> 9, rem = u & 511, r = rem >> 3, ch = rem & 7;
        int nn = n0 + r, m = ch * 2;
        float2 v = make_float2(0.f, 0.f);
        if (nn < NF && m < NF)
            v = *reinterpret_cast<const float2*>(A + ((size_t)(b * HH + hh) * NF + nn) * NF + m);
        aF[k] = v;
    }
#pragma unroll
    for (int k = 0; k < 4; k++) {
        int q = tid + (k << 8);
        int j = q >> 6, cg = (q & 63) << 2;
        const float* src = g_xt + ((size_t)b * NF + j) * HD + cg;
        asm volatile("cp.async.cg.shared.global [%0], [%1], 16, %2;"
                     :: "r"(sbase + (unsigned)(j * 256 + cg) * 4u), "l"(src), "r"(16));
    }
    asm volatile("cp.async.commit_group;" ::: "memory");

    for (int t = 0; t < 32; t++) {
        int cur = t & 1;
        asm volatile("cp.async.wait_group 0;" ::: "memory");

        {
            float* Asb = sb + 8192 + cur * 4224;
#pragma unroll
            for (int k = 0; k < 8; k++) {
                int u = tid + (k << 8);
                int hh = u >> 9, rem = u & 511, r = rem >> 3, ch = rem & 7;
                float* dst = Asb + (hh * 16 + ch * 2) * 66 + r;
                dst[0] = aF[k].x;
                dst[66] = aF[k].y;
            }
        }
        __syncthreads();

        if (t < 31) {
            int m0n = (t + 1) << 4;
            unsigned xd = sbase + (unsigned)((cur ^ 1) * 4096) * 4u;
#pragma unroll
            for (int k = 0; k < 4; k++) {
                int q = tid + (k << 8);
                int j = q >> 6, cg = (q & 63) << 2;
                int m = m0n + j;
                int mc = (m < NF) ? m : 0;
                const float* src = g_xt + ((size_t)b * NF + mc) * HD + cg;
                int sz = (m < NF) ? 16 : 0;
                asm volatile("cp.async.cg.shared.global [%0], [%1], 16, %2;"
                             :: "r"(xd + (unsigned)(j * 256 + cg) * 4u), "l"(src), "r"(sz));
            }
            asm volatile("cp.async.commit_group;" ::: "memory");
#pragma unroll
            for (int k = 0; k < 8; k++) {
                int u = tid + (k << 8);
                int hh = u >> 9, rem = u & 511, r = rem >> 3, ch = rem & 7;
                int nn = n0 + r, m = m0n + ch * 2;
                float2 v = make_float2(0.f, 0.f);
                if (nn < NF && m < NF)
                    v = *reinterpret_cast<const float2*>(A + ((size_t)(b * HH + hh) * NF + nn) * NF + m);
                aF[k] = v;
            }
        }

        {
            const float* xb = sb + cur * 4096;
            const float* Ab = sb + 8192 + cur * 4224 + (h * 16) * 66 + rg * 32;
#pragma unroll 4
            for (int j = 0; j < 16; j++) {
                float2 xv = *reinterpret_cast<const float2*>(xb + j * 256 + 2 * cp);
                ull x0 = pack2(xv.x, xv.x);
                ull x1 = pack2(xv.y, xv.y);
                const float* Ar = Ab + j * 66;
#pragma unroll
                for (int p = 0; p < 16; p++) {
                    ull a2 = *reinterpret_cast<const ull*>(Ar + 2 * p);
                    fma2(acc[p][0], a2, x0);
                    fma2(acc[p][1], a2, x1);
                }
            }
        }
    }
    __syncthreads();

#pragma unroll
    for (int p = 0; p < 16; p++) {
        int row = rg * 32 + 2 * p;
        float2 a0 = unpack2(acc[p][0]);
        float2 a1 = unpack2(acc[p][1]);
        *reinterpret_cast<float2*>(sb + row * 256 + 2 * cp) = make_float2(a0.x, a1.x);
        *reinterpret_cast<float2*>(sb + (row + 1) * 256 + 2 * cp) = make_float2(a0.y, a1.y);
    }
    __syncthreads();
#pragma unroll
    for (int k = 0; k < 16; k++) {
        int o = tid + (k << 8);
        int r = o >> 6, d = o & 63;
        int nn = n0 + r;
        if (nn < NF) {
            float s = sb[r * 256 + d] + sb[r * 256 + d + 64] +
                      sb[r * 256 + d + 128] + sb[r * 256 + d + 192];
            g_out[((size_t)b * NF + nn) * DD + d] = 0.25f * s;
        }
    }
}

// ---------------------------------------------------------------------------
// K4: g = out @ fcg_w + fcg_b; GLU; residual; LayerNorm. 8 rows/block.
// ---------------------------------------------------------------------------
__global__ void k4_glu_ln(const float* __restrict__ x,
                          const float* __restrict__ fw, const float* __restrict__ fb,
                          const float* __restrict__ lgm, const float* __restrict__ lbt,
                          float* __restrict__ y) {
    int bn0 = blockIdx.x << 3;
    int tid = threadIdx.x;  // 256
    __shared__ __align__(16) float fws[DD * 128];
    __shared__ __align__(8) float orowT[DD][10];
    __shared__ float gsh[8][128];

#pragma unroll
    for (int k = 0; k < 8; k++) {
        int f = (tid + (k << 8)) << 2;
        *reinterpret_cast<float4*>(fws + f) = *reinterpret_cast<const float4*>(fw + f);
    }
#pragma unroll
    for (int k = 0; k < 2; k++) {
        int i = tid + (k << 8);
        int rr = i >> 6, d = i & 63;
        orowT[d][rr] = g_out[(size_t)(bn0 + rr) * DD + d];
    }
    __syncthreads();

    int col = tid & 127, rh = tid >> 7;
    float fbv = fb[col];
    ull acc01 = pack2(fbv, fbv);
    ull acc23 = pack2(fbv, fbv);
#pragma unroll
    for (int d = 0; d < DD; d++) {
        float fv = fws[d * 128 + col];
        ull fv2 = pack2(fv, fv);
        ull o01 = *reinterpret_cast<const ull*>(&orowT[d][rh * 4]);
        ull o23 = *reinterpret_cast<const ull*>(&orowT[d][rh * 4 + 2]);
        fma2(acc01, o01, fv2);
        fma2(acc23, o23, fv2);
    }
    {
        float2 v01 = unpack2(acc01);
        float2 v23 = unpack2(acc23);
        gsh[rh * 4 + 0][col] = v01.x;
        gsh[rh * 4 + 1][col] = v01.y;
        gsh[rh * 4 + 2][col] = v23.x;
        gsh[rh * 4 + 3][col] = v23.y;
    }
    __syncthreads();

    int w = tid >> 5, l = tid & 31;
    int bn = bn0 + w;
    float yv0, yv1;
    {
        float a0 = gsh[w][l],      b0 = gsh[w][l + 64];
        float a1 = gsh[w][l + 32], b1 = gsh[w][l + 96];
        float s0 = 1.f / (1.f + __expf(-b0));
        float s1 = 1.f / (1.f + __expf(-b1));
        yv0 = fmaf(a0, s0, x[(size_t)bn * DD + l]);
        yv1 = fmaf(a1, s1, x[(size_t)bn * DD + l + 32]);
    }
    float s = yv0 + yv1;
#pragma unroll
    for (int o = 16; o; o >>= 1) s += __shfl_xor_sync(0xffffffffu, s, o);
    float mu = s * (1.f / 64.f);
    float d0 = yv0 - mu, d1 = yv1 - mu;
    float q = d0 * d0 + d1 * d1;
#pragma unroll
    for (int o = 16; o; o >>= 1) q += __shfl_xor_sync(0xffffffffu, q, o);
    float rs = rsqrtf(q * (1.f / 64.f) + 1e-5f);
    y[(size_t)bn * DD + l]      = d0 * rs * lgm[l]      + lbt[l];
    y[(size_t)bn * DD + l + 32] = d1 * rs * lgm[l + 32] + lbt[l + 32];
}

// ---------------------------------------------------------------------------
extern "C" void kernel_launch(void* const* d_in, const int* in_sizes, int n_in,
                              void* d_out, int out_size) {
    const float* x      = (const float*)d_in[0];
    const float* causal = (const float*)d_in[1];
    const float* W      = (const float*)d_in[2];
    const float* attw   = (const float*)d_in[3];
    const float* conv_w = (const float*)d_in[4];
    const float* conv_b = (const float*)d_in[5];
    const float* fcg_w  = (const float*)d_in[6];
    const float* fcg_b  = (const float*)d_in[7];
    const float* ln_g   = (const float*)d_in[8];
    const float* ln_b   = (const float*)d_in[9];

    float* y = (float*)d_out;
    float* A = (float*)d_out + (size_t)BB * NF * DD;   // (y, A) flattened in order

    cudaFuncSetAttribute(k3_apply, cudaFuncAttributeMaxDynamicSharedMemorySize, 66560);

    k1_proj<<<(BB * NF) / 8, 256>>>(x, W, attw);
    k2a_cconv<<<NF, 256>>>(causal, conv_w, conv_b);
    k2_attn<<<dim3(64, BB), 256>>>(conv_w, A);
    k3_apply<<<dim3(8, BB), 256, 66560>>>(A);
    k4_glu_ln<<<(BB * NF) / 8, 256>>>(x, fcg_w, fcg_b, ln_g, ln_b, y);
}

// round 11
// speedup vs baseline: 1.7536x; 1.0077x over previous
#include <cuda_runtime.h>

#define NF 510
#define BB 32
#define DD 64
#define HH 4
#define HD 256   // H*D

typedef unsigned long long ull;

// Scratch (static device arrays are the sanctioned workaround)
__device__ float g_xt[(size_t)BB * NF * HD];        // (b, n, h*64+d)
__device__ float g_si[BB * HH * NF];
__device__ float g_sj[BB * HH * NF];
__device__ float g_out[(size_t)BB * NF * DD];
__device__ float g_cconv[(size_t)HH * NF * NF];     // 0.9*(conv(causal)+bias), b-independent

__device__ __forceinline__ ull pack2(float a, float b) {
    ull r; asm("mov.b64 %0, {%1, %2};" : "=l"(r) : "f"(a), "f"(b)); return r;
}
__device__ __forceinline__ void fma2(ull& acc, ull a, ull b) {
    asm("fma.rn.f32x2 %0, %1, %2, %0;" : "+l"(acc) : "l"(a), "l"(b));
}
__device__ __forceinline__ float2 unpack2(ull v) {
    float2 f; asm("mov.b64 {%0, %1}, %2;" : "=f"(f.x), "=f"(f.y) : "l"(v)); return f;
}

// ---------------------------------------------------------------------------
// K1: xt = x @ W  (+ s_i, s_j head scores). 8 rows/block, f32x2 row pairs.
// ---------------------------------------------------------------------------
__global__ void k1_proj(const float* __restrict__ x, const float* __restrict__ W,
                        const float* __restrict__ attw) {
    int bn0 = blockIdx.x << 3;
    int tid = threadIdx.x;              // 256, col = tid
    __shared__ __align__(8) float xs[DD][10];
    __shared__ float red[8][8][2];

#pragma unroll
    for (int k = 0; k < 2; k++) {
        int i = tid + (k << 8);
        int r = i >> 6, d = i & 63;
        xs[d][r] = x[(size_t)(bn0 + r) * DD + d];
    }
    __syncthreads();

    ull acc[4] = {0ull, 0ull, 0ull, 0ull};
#pragma unroll
    for (int d = 0; d < DD; d++) {
        float wv = W[d * HD + tid];
        ull wv2 = pack2(wv, wv);
#pragma unroll
        for (int p = 0; p < 4; p++) {
            ull xp = *reinterpret_cast<const ull*>(&xs[d][2 * p]);
            fma2(acc[p], xp, wv2);
        }
    }
    float accs[8];
#pragma unroll
    for (int p = 0; p < 4; p++) {
        float2 v = unpack2(acc[p]);
        accs[2 * p] = v.x; accs[2 * p + 1] = v.y;
    }
#pragma unroll
    for (int r = 0; r < 8; r++)
        g_xt[(size_t)(bn0 + r) * HD + tid] = accs[r];

    int h = tid >> 6, dd = tid & 63;
    float w1 = attw[h * 128 + dd];
    float w2 = attw[h * 128 + 64 + dd];
    int wid = tid >> 5, lane = tid & 31;
#pragma unroll
    for (int r = 0; r < 8; r++) {
        float v1 = accs[r] * w1;
        float v2 = accs[r] * w2;
#pragma unroll
        for (int o = 16; o; o >>= 1) {
            v1 += __shfl_xor_sync(0xffffffffu, v1, o);
            v2 += __shfl_xor_sync(0xffffffffu, v2, o);
        }
        if (lane == 0) { red[r][wid][0] = v1; red[r][wid][1] = v2; }
    }
    __syncthreads();
    if (tid < 32) {
        int r = tid >> 2, hh = tid & 3;
        int bn = bn0 + r;
        int b = bn / NF, n = bn - b * NF;
        g_si[(b * HH + hh) * NF + n] = red[r][2 * hh][0] + red[r][2 * hh + 1][0];
        g_sj[(b * HH + hh) * NF + n] = red[r][2 * hh][1] + red[r][2 * hh + 1][1];
    }
}

// ---------------------------------------------------------------------------
// K2a: 0.9 * (causal-channel conv + bias), b-independent, once per (h,n,m).
// ---------------------------------------------------------------------------
__global__ void k2a_cconv(const float* __restrict__ causal,
                          const float* __restrict__ conv_w,
                          const float* __restrict__ conv_b) {
    int n = blockIdx.x;
    int tid = threadIdx.x;  // 256
    __shared__ float caus[3][512];
    __shared__ float cw[72];
    __shared__ float cb[4];

    if (tid < 72) cw[tid] = conv_w[tid];
    if (tid >= 96 && tid < 100) cb[tid - 96] = conv_b[tid - 96];
    for (int i = tid; i < 3 * 512; i += 256) {
        int rr = i >> 9, mm = i & 511;
        int r = n - 1 + rr, m = mm - 1;
        caus[rr][mm] = (r >= 0 && r < NF && m >= 0 && m < NF) ? causal[r * NF + m] : 0.f;
    }
    __syncthreads();

#pragma unroll
    for (int s = 0; s < 2; s++) {
        int m = tid + (s << 8);
        if (m < NF) {
#pragma unroll
            for (int h = 0; h < HH; h++) {
                float st = cb[h];
#pragma unroll
                for (int rr = 0; rr < 3; rr++)
#pragma unroll
                    for (int dj = 0; dj < 3; dj++)
                        st = fmaf(cw[((h * 2 + 1) * 3 + rr) * 3 + dj], caus[rr][m + dj], st);
                g_cconv[((size_t)h * NF + n) * NF + m] = 0.9f * st;
            }
        }
    }
}

// ---------------------------------------------------------------------------
// K2: 8 n-rows per block, one warp per row. amean rows n0-1..n0+8 computed
// in smem from si/sj. Per warp: head-pairs, logits in registers, warp-level
// softmax (no block barriers in the main loop). Writes A.
// ---------------------------------------------------------------------------
__global__ __launch_bounds__(256) void k2_attn(const float* __restrict__ conv_w,
                                               float* __restrict__ A_out) {
    int b = blockIdx.y;
    int n0 = blockIdx.x << 3;
    int tid = threadIdx.x;  // 256
    int wid = tid >> 5, lane = tid & 31;

    __shared__ float sjs[HH][512];
    __shared__ float am[10][512];     // rows n0-1 .. n0+8; col mm = m+1... no: col = m directly? see below
    __shared__ float cw9[HH][9];      // 0.9 * amean-channel conv weights
    __shared__ float si_blk[10][HH];  // si rows n0-1 .. n0+8

    if (tid < 36) {
        int h = tid / 9, k = tid - h * 9;
        cw9[h][k] = 0.9f * conv_w[h * 18 + k];
    }
    if (tid >= 64 && tid < 104) {
        int t = tid - 64, rr = t >> 2, h = t & 3;
        int r = n0 - 1 + rr;
        si_blk[rr][h] = (r >= 0 && r < NF) ? g_si[(b * HH + h) * NF + r] : 0.f;
    }
    for (int i = tid; i < HH * 512; i += 256) {
        int h = i >> 9, m = i & 511;
        sjs[h][m] = (m < NF) ? g_sj[(b * HH + h) * NF + m] : 0.f;
    }
    __syncthreads();

    // amean rows: am[rr][mm], mm = m+1 (mm 0 and 511 are zero pads)
    for (int i = tid; i < 10 * 512; i += 256) {
        int rr = i / 512, mm = i - rr * 512;
        int r = n0 - 1 + rr, m = mm - 1;
        float a = 0.f;
        if (r >= 0 && r < NF && m >= 0 && m < NF) {
#pragma unroll
            for (int h = 0; h < HH; h++) {
                float e = si_blk[rr][h] + sjs[h][m];
                a += (e >= 0.f) ? e : 0.01f * e;
            }
            a *= 0.25f;
        }
        am[rr][mm] = a;
    }
    __syncthreads();

    int n = n0 + wid;
    bool active = n < NF;
    float si1[HH];
#pragma unroll
    for (int h = 0; h < HH; h++) si1[h] = si_blk[wid + 1][h];

#pragma unroll
    for (int hp = 0; hp < 2; hp++) {
        int h0 = hp << 1, h1 = h0 + 1;
        const float* cc0 = g_cconv + ((size_t)h0 * NF + n) * NF;
        const float* cc1 = g_cconv + ((size_t)h1 * NF + n) * NF;
        float lg0[16], lg1[16];
        float mx0 = -1e30f, mx1 = -1e30f;

#pragma unroll
        for (int c = 0; c < 16; c++) {
            int m = (c << 5) + lane;
            float l0 = -1e30f, l1 = -1e30f;
            if (active && m < NF) {
                // conv taps at am[wid + rr][m + dj]  (mm = m+1 -> taps m..m+2)
                float st0 = cc0[m];
                float st1 = cc1[m];
#pragma unroll
                for (int rr = 0; rr < 3; rr++) {
                    float a0 = am[wid + rr][m];
                    float a1 = am[wid + rr][m + 1];
                    float a2 = am[wid + rr][m + 2];
                    st0 = fmaf(cw9[h0][rr * 3 + 0], a0, st0);
                    st0 = fmaf(cw9[h0][rr * 3 + 1], a1, st0);
                    st0 = fmaf(cw9[h0][rr * 3 + 2], a2, st0);
                    st1 = fmaf(cw9[h1][rr * 3 + 0], a0, st1);
                    st1 = fmaf(cw9[h1][rr * 3 + 1], a1, st1);
                    st1 = fmaf(cw9[h1][rr * 3 + 2], a2, st1);
                }
                float e0 = si1[h0] + sjs[h0][m];
                float e1 = si1[h1] + sjs[h1][m];
                float av0 = (e0 >= 0.f) ? e0 : 0.01f * e0;
                float av1 = (e1 >= 0.f) ? e1 : 0.01f * e1;
                l0 = fmaf(0.1f, av0, st0);
                l1 = fmaf(0.1f, av1, st1);
            }
            lg0[c] = l0; lg1[c] = l1;
            mx0 = fmaxf(mx0, l0); mx1 = fmaxf(mx1, l1);
        }

#pragma unroll
        for (int o = 16; o; o >>= 1) {
            mx0 = fmaxf(mx0, __shfl_xor_sync(0xffffffffu, mx0, o));
            mx1 = fmaxf(mx1, __shfl_xor_sync(0xffffffffu, mx1, o));
        }
        float s0 = 0.f, s1 = 0.f;
#pragma unroll
        for (int c = 0; c < 16; c++) {
            float e0 = __expf(lg0[c] - mx0);
            float e1 = __expf(lg1[c] - mx1);
            lg0[c] = e0; lg1[c] = e1;
            s0 += e0; s1 += e1;
        }
#pragma unroll
        for (int o = 16; o; o >>= 1) {
            s0 += __shfl_xor_sync(0xffffffffu, s0, o);
            s1 += __shfl_xor_sync(0xffffffffu, s1, o);
        }
        float inv0 = __frcp_rn(s0);
        float inv1 = __frcp_rn(s1);

        if (active) {
            float* d0 = A_out + ((size_t)(b * HH + h0) * NF + n) * NF;
            float* d1 = A_out + ((size_t)(b * HH + h1) * NF + n) * NF;
#pragma unroll
            for (int c = 0; c < 16; c++) {
                int m = (c << 5) + lane;
                if (m < NF) {
                    d0[m] = lg0[c] * inv0;
                    d1[m] = lg1[c] * inv1;
                }
            }
        }
    }
}

// ---------------------------------------------------------------------------
// K3: out[b,n,d] = 0.25 * sum_h sum_m A[b,h,n,m] * xt[b,m,h,d]
// 64-row blocks, 16 row-pairs x 2 cols per thread, cp.async double-buffered.
// ---------------------------------------------------------------------------
__global__ __launch_bounds__(256, 2) void k3_apply(const float* __restrict__ A) {
    extern __shared__ __align__(16) float sb[];
    int b = blockIdx.y;
    int n0 = blockIdx.x << 6;     // 64 rows
    int tid = threadIdx.x;        // 256
    int cp = tid & 127, rg = tid >> 7, h = cp >> 5;
    unsigned sbase = (unsigned)__cvta_generic_to_shared(sb);

    ull acc[16][2];
#pragma unroll
    for (int p = 0; p < 16; p++) { acc[p][0] = 0ull; acc[p][1] = 0ull; }

    float2 aF[8];

#pragma unroll
    for (int k = 0; k < 8; k++) {
        int u = tid + (k << 8);
        int hh = u >> 9, rem = u & 511, r = rem >> 3, ch = rem & 7;
        int nn = n0 + r, m = ch * 2;
        float2 v = make_float2(0.f, 0.f);
        if (nn < NF && m < NF)
            v = *reinterpret_cast<const float2*>(A + ((size_t)(b * HH + hh) * NF + nn) * NF + m);
        aF[k] = v;
    }
#pragma unroll
    for (int k = 0; k < 4; k++) {
        int q = tid + (k << 8);
        int j = q >> 6, cg = (q & 63) << 2;
        const float* src = g_xt + ((size_t)b * NF + j) * HD + cg;
        asm volatile("cp.async.cg.shared.global [%0], [%1], 16, %2;"
                     :: "r"(sbase + (unsigned)(j * 256 + cg) * 4u), "l"(src), "r"(16));
    }
    asm volatile("cp.async.commit_group;" ::: "memory");

    for (int t = 0; t < 32; t++) {
        int cur = t & 1;
        asm volatile("cp.async.wait_group 0;" ::: "memory");

        {
            float* Asb = sb + 8192 + cur * 4224;
#pragma unroll
            for (int k = 0; k < 8; k++) {
                int u = tid + (k << 8);
                int hh = u >> 9, rem = u & 511, r = rem >> 3, ch = rem & 7;
                float* dst = Asb + (hh * 16 + ch * 2) * 66 + r;
                dst[0] = aF[k].x;
                dst[66] = aF[k].y;
            }
        }
        __syncthreads();

        if (t < 31) {
            int m0n = (t + 1) << 4;
            unsigned xd = sbase + (unsigned)((cur ^ 1) * 4096) * 4u;
#pragma unroll
            for (int k = 0; k < 4; k++) {
                int q = tid + (k << 8);
                int j = q >> 6, cg = (q & 63) << 2;
                int m = m0n + j;
                int mc = (m < NF) ? m : 0;
                const float* src = g_xt + ((size_t)b * NF + mc) * HD + cg;
                int sz = (m < NF) ? 16 : 0;
                asm volatile("cp.async.cg.shared.global [%0], [%1], 16, %2;"
                             :: "r"(xd + (unsigned)(j * 256 + cg) * 4u), "l"(src), "r"(sz));
            }
            asm volatile("cp.async.commit_group;" ::: "memory");
#pragma unroll
            for (int k = 0; k < 8; k++) {
                int u = tid + (k << 8);
                int hh = u >> 9, rem = u & 511, r = rem >> 3, ch = rem & 7;
                int nn = n0 + r, m = m0n + ch * 2;
                float2 v = make_float2(0.f, 0.f);
                if (nn < NF && m < NF)
                    v = *reinterpret_cast<const float2*>(A + ((size_t)(b * HH + hh) * NF + nn) * NF + m);
                aF[k] = v;
            }
        }

        {
            const float* xb = sb + cur * 4096;
            const float* Ab = sb + 8192 + cur * 4224 + (h * 16) * 66 + rg * 32;
#pragma unroll 4
            for (int j = 0; j < 16; j++) {
                float2 xv = *reinterpret_cast<const float2*>(xb + j * 256 + 2 * cp);
                ull x0 = pack2(xv.x, xv.x);
                ull x1 = pack2(xv.y, xv.y);
                const float* Ar = Ab + j * 66;
#pragma unroll
                for (int p = 0; p < 16; p++) {
                    ull a2 = *reinterpret_cast<const ull*>(Ar + 2 * p);
                    fma2(acc[p][0], a2, x0);
                    fma2(acc[p][1], a2, x1);
                }
            }
        }
    }
    __syncthreads();

#pragma unroll
    for (int p = 0; p < 16; p++) {
        int row = rg * 32 + 2 * p;
        float2 a0 = unpack2(acc[p][0]);
        float2 a1 = unpack2(acc[p][1]);
        *reinterpret_cast<float2*>(sb + row * 256 + 2 * cp) = make_float2(a0.x, a1.x);
        *reinterpret_cast<float2*>(sb + (row + 1) * 256 + 2 * cp) = make_float2(a0.y, a1.y);
    }
    __syncthreads();
#pragma unroll
    for (int k = 0; k < 16; k++) {
        int o = tid + (k << 8);
        int r = o >> 6, d = o & 63;
        int nn = n0 + r;
        if (nn < NF) {
            float s = sb[r * 256 + d] + sb[r * 256 + d + 64] +
                      sb[r * 256 + d + 128] + sb[r * 256 + d + 192];
            g_out[((size_t)b * NF + nn) * DD + d] = 0.25f * s;
        }
    }
}

// ---------------------------------------------------------------------------
// K4: g = out @ fcg_w + fcg_b; GLU; residual; LayerNorm. 8 rows/block.
// ---------------------------------------------------------------------------
__global__ void k4_glu_ln(const float* __restrict__ x,
                          const float* __restrict__ fw, const float* __restrict__ fb,
                          const float* __restrict__ lgm, const float* __restrict__ lbt,
                          float* __restrict__ y) {
    int bn0 = blockIdx.x << 3;
    int tid = threadIdx.x;  // 256
    __shared__ __align__(16) float fws[DD * 128];
    __shared__ __align__(8) float orowT[DD][10];
    __shared__ float gsh[8][128];

#pragma unroll
    for (int k = 0; k < 8; k++) {
        int f = (tid + (k << 8)) << 2;
        *reinterpret_cast<float4*>(fws + f) = *reinterpret_cast<const float4*>(fw + f);
    }
#pragma unroll
    for (int k = 0; k < 2; k++) {
        int i = tid + (k << 8);
        int rr = i >> 6, d = i & 63;
        orowT[d][rr] = g_out[(size_t)(bn0 + rr) * DD + d];
    }
    __syncthreads();

    int col = tid & 127, rh = tid >> 7;
    float fbv = fb[col];
    ull acc01 = pack2(fbv, fbv);
    ull acc23 = pack2(fbv, fbv);
#pragma unroll
    for (int d = 0; d < DD; d++) {
        float fv = fws[d * 128 + col];
        ull fv2 = pack2(fv, fv);
        ull o01 = *reinterpret_cast<const ull*>(&orowT[d][rh * 4]);
        ull o23 = *reinterpret_cast<const ull*>(&orowT[d][rh * 4 + 2]);
        fma2(acc01, o01, fv2);
        fma2(acc23, o23, fv2);
    }
    {
        float2 v01 = unpack2(acc01);
        float2 v23 = unpack2(acc23);
        gsh[rh * 4 + 0][col] = v01.x;
        gsh[rh * 4 + 1][col] = v01.y;
        gsh[rh * 4 + 2][col] = v23.x;
        gsh[rh * 4 + 3][col] = v23.y;
    }
    __syncthreads();

    int w = tid >> 5, l = tid & 31;
    int bn = bn0 + w;
    float yv0, yv1;
    {
        float a0 = gsh[w][l],      b0 = gsh[w][l + 64];
        float a1 = gsh[w][l + 32], b1 = gsh[w][l + 96];
        float s0 = 1.f / (1.f + __expf(-b0));
        float s1 = 1.f / (1.f + __expf(-b1));
        yv0 = fmaf(a0, s0, x[(size_t)bn * DD + l]);
        yv1 = fmaf(a1, s1, x[(size_t)bn * DD + l + 32]);
    }
    float s = yv0 + yv1;
#pragma unroll
    for (int o = 16; o; o >>= 1) s += __shfl_xor_sync(0xffffffffu, s, o);
    float mu = s * (1.f / 64.f);
    float d0 = yv0 - mu, d1 = yv1 - mu;
    float q = d0 * d0 + d1 * d1;
#pragma unroll
    for (int o = 16; o; o >>= 1) q += __shfl_xor_sync(0xffffffffu, q, o);
    float rs = rsqrtf(q * (1.f / 64.f) + 1e-5f);
    y[(size_t)bn * DD + l]      = d0 * rs * lgm[l]      + lbt[l];
    y[(size_t)bn * DD + l + 32] = d1 * rs * lgm[l + 32] + lbt[l + 32];
}

// ---------------------------------------------------------------------------
extern "C" void kernel_launch(void* const* d_in, const int* in_sizes, int n_in,
                              void* d_out, int out_size) {
    const float* x      = (const float*)d_in[0];
    const float* causal = (const float*)d_in[1];
    const float* W      = (const float*)d_in[2];
    const float* attw   = (const float*)d_in[3];
    const float* conv_w = (const float*)d_in[4];
    const float* conv_b = (const float*)d_in[5];
    const float* fcg_w  = (const float*)d_in[6];
    const float* fcg_b  = (const float*)d_in[7];
    const float* ln_g   = (const float*)d_in[8];
    const float* ln_b   = (const float*)d_in[9];

    float* y = (float*)d_out;
    float* A = (float*)d_out + (size_t)BB * NF * DD;   // (y, A) flattened in order

    cudaFuncSetAttribute(k3_apply, cudaFuncAttributeMaxDynamicSharedMemorySize, 66560);

    k1_proj<<<(BB * NF) / 8, 256>>>(x, W, attw);
    k2a_cconv<<<NF, 256>>>(causal, conv_w, conv_b);
    k2_attn<<<dim3(64, BB), 256>>>(conv_w, A);
    k3_apply<<<dim3(8, BB), 256, 66560>>>(A);
    k4_glu_ln<<<(BB * NF) / 8, 256>>>(x, fcg_w, fcg_b, ln_g, ln_b, y);
}

// round 16
// speedup vs baseline: 2.1936x; 1.2509x over previous
#include <cuda_runtime.h>
#include <cstdint>

#define NF 510
#define BB 32
#define DD 64
#define HH 4
#define HD 256   // H*D
#define XTP 512  // padded m-stride of split xt

typedef unsigned long long ull;

__device__ float g_xt[(size_t)BB * NF * HD];        // (b, n, h*64+d)
__device__ float g_si[BB * HH * NF];
__device__ float g_sj[BB * HH * NF];
__device__ float g_out[(size_t)BB * NF * DD];
__device__ float g_cconv[(size_t)HH * NF * NF];     // 0.9*(conv(causal)+bias)
__device__ uint16_t g_xth[(size_t)BB * HH * DD * XTP];  // bf16 hi, [b][h][d][m]
__device__ uint16_t g_xtl[(size_t)BB * HH * DD * XTP];  // bf16 lo

__device__ __forceinline__ ull pack2(float a, float b) {
    ull r; asm("mov.b64 %0, {%1, %2};" : "=l"(r) : "f"(a), "f"(b)); return r;
}
__device__ __forceinline__ void fma2(ull& acc, ull a, ull b) {
    asm("fma.rn.f32x2 %0, %1, %2, %0;" : "+l"(acc) : "l"(a), "l"(b));
}
__device__ __forceinline__ float2 unpack2(ull v) {
    float2 f; asm("mov.b64 {%0, %1}, %2;" : "=f"(f.x), "=f"(f.y) : "l"(v)); return f;
}
__device__ __forceinline__ unsigned cvt2bf(float hi_, float lo_) {
    unsigned r; asm("cvt.rn.bf16x2.f32 %0, %1, %2;" : "=r"(r) : "f"(hi_), "f"(lo_)); return r;
}
// v0 -> lower bf16, v1 -> upper; lo = residual pair
__device__ __forceinline__ void split2(float v0, float v1, unsigned& hi, unsigned& lo) {
    hi = cvt2bf(v1, v0);
    float h0 = __uint_as_float(hi << 16);
    float h1 = __uint_as_float(hi & 0xFFFF0000u);
    lo = cvt2bf(v1 - h1, v0 - h0);
}

// ---------------------------------------------------------------------------
// K1: xt = x @ W  (+ s_i, s_j head scores). 8 rows/block, f32x2 row pairs.
// ---------------------------------------------------------------------------
__global__ void k1_proj(const float* __restrict__ x, const float* __restrict__ W,
                        const float* __restrict__ attw) {
    int bn0 = blockIdx.x << 3;
    int tid = threadIdx.x;
    __shared__ __align__(8) float xs[DD][10];
    __shared__ float red[8][8][2];

#pragma unroll
    for (int k = 0; k < 2; k++) {
        int i = tid + (k << 8);
        int r = i >> 6, d = i & 63;
        xs[d][r] = x[(size_t)(bn0 + r) * DD + d];
    }
    __syncthreads();

    ull acc[4] = {0ull, 0ull, 0ull, 0ull};
#pragma unroll
    for (int d = 0; d < DD; d++) {
        float wv = W[d * HD + tid];
        ull wv2 = pack2(wv, wv);
#pragma unroll
        for (int p = 0; p < 4; p++) {
            ull xp = *reinterpret_cast<const ull*>(&xs[d][2 * p]);
            fma2(acc[p], xp, wv2);
        }
    }
    float accs[8];
#pragma unroll
    for (int p = 0; p < 4; p++) {
        float2 v = unpack2(acc[p]);
        accs[2 * p] = v.x; accs[2 * p + 1] = v.y;
    }
#pragma unroll
    for (int r = 0; r < 8; r++)
        g_xt[(size_t)(bn0 + r) * HD + tid] = accs[r];

    int h = tid >> 6, dd = tid & 63;
    float w1 = attw[h * 128 + dd];
    float w2 = attw[h * 128 + 64 + dd];
    int wid = tid >> 5, lane = tid & 31;
#pragma unroll
    for (int r = 0; r < 8; r++) {
        float v1 = accs[r] * w1;
        float v2 = accs[r] * w2;
#pragma unroll
        for (int o = 16; o; o >>= 1) {
            v1 += __shfl_xor_sync(0xffffffffu, v1, o);
            v2 += __shfl_xor_sync(0xffffffffu, v2, o);
        }
        if (lane == 0) { red[r][wid][0] = v1; red[r][wid][1] = v2; }
    }
    __syncthreads();
    if (tid < 32) {
        int r = tid >> 2, hh = tid & 3;
        int bn = bn0 + r;
        int b = bn / NF, n = bn - b * NF;
        g_si[(b * HH + hh) * NF + n] = red[r][2 * hh][0] + red[r][2 * hh + 1][0];
        g_sj[(b * HH + hh) * NF + n] = red[r][2 * hh][1] + red[r][2 * hh + 1][1];
    }
}

// ---------------------------------------------------------------------------
// K1b: transpose + bf16 hi/lo split of xt: g_xt[b][m][h*64+d] -> g_xth/l
// [b][h][d][m] (m padded to 512, zero tail). Coalesced both sides via smem.
// ---------------------------------------------------------------------------
__global__ void k1b_split() {
    int b = blockIdx.y >> 2, h = blockIdx.y & 3;
    int m0 = blockIdx.x << 6;
    int tid = threadIdx.x;  // 256
    __shared__ float T[64][65];

#pragma unroll
    for (int k = 0; k < 16; k++) {
        int gid = tid + (k << 8);
        int m = gid >> 6, d = gid & 63;
        int mg = m0 + m;
        T[m][d] = (mg < NF) ? g_xt[((size_t)b * NF + mg) * HD + (h << 6) + d] : 0.f;
    }
    __syncthreads();

    size_t rbase = (size_t)(b * HH + h) * DD * XTP;
#pragma unroll
    for (int k = 0; k < 8; k++) {
        int gid = tid + (k << 8);
        int d = gid >> 5, pc = gid & 31;
        unsigned hi, lo;
        split2(T[2 * pc][d], T[2 * pc + 1][d], hi, lo);
        size_t w = (rbase + (size_t)d * XTP + m0) / 2 + pc;   // u32 index
        reinterpret_cast<unsigned*>(g_xth)[w] = hi;
        reinterpret_cast<unsigned*>(g_xtl)[w] = lo;
    }
}

// ---------------------------------------------------------------------------
// K2a: 0.9 * (causal-channel conv + bias), b-independent.
// ---------------------------------------------------------------------------
__global__ void k2a_cconv(const float* __restrict__ causal,
                          const float* __restrict__ conv_w,
                          const float* __restrict__ conv_b) {
    int n = blockIdx.x;
    int tid = threadIdx.x;
    __shared__ float caus[3][512];
    __shared__ float cw[72];
    __shared__ float cb[4];

    if (tid < 72) cw[tid] = conv_w[tid];
    if (tid >= 96 && tid < 100) cb[tid - 96] = conv_b[tid - 96];
    for (int i = tid; i < 3 * 512; i += 256) {
        int rr = i >> 9, mm = i & 511;
        int r = n - 1 + rr, m = mm - 1;
        caus[rr][mm] = (r >= 0 && r < NF && m >= 0 && m < NF) ? causal[r * NF + m] : 0.f;
    }
    __syncthreads();

#pragma unroll
    for (int s = 0; s < 2; s++) {
        int m = tid + (s << 8);
        if (m < NF) {
#pragma unroll
            for (int h = 0; h < HH; h++) {
                float st = cb[h];
#pragma unroll
                for (int rr = 0; rr < 3; rr++)
#pragma unroll
                    for (int dj = 0; dj < 3; dj++)
                        st = fmaf(cw[((h * 2 + 1) * 3 + rr) * 3 + dj], caus[rr][m + dj], st);
                g_cconv[((size_t)h * NF + n) * NF + m] = 0.9f * st;
            }
        }
    }
}

// ---------------------------------------------------------------------------
// K2: 8 n-rows per block, one warp per row; warp-level softmax. Writes A.
// ---------------------------------------------------------------------------
__global__ __launch_bounds__(256) void k2_attn(const float* __restrict__ conv_w,
                                               float* __restrict__ A_out) {
    int b = blockIdx.y;
    int n0 = blockIdx.x << 3;
    int tid = threadIdx.x;
    int wid = tid >> 5, lane = tid & 31;

    __shared__ float sjs[HH][512];
    __shared__ float am[10][512];
    __shared__ float cw9[HH][9];
    __shared__ float si_blk[10][HH];

    if (tid < 36) {
        int h = tid / 9, k = tid - h * 9;
        cw9[h][k] = 0.9f * conv_w[h * 18 + k];
    }
    if (tid >= 64 && tid < 104) {
        int t = tid - 64, rr = t >> 2, h = t & 3;
        int r = n0 - 1 + rr;
        si_blk[rr][h] = (r >= 0 && r < NF) ? g_si[(b * HH + h) * NF + r] : 0.f;
    }
    for (int i = tid; i < HH * 512; i += 256) {
        int h = i >> 9, m = i & 511;
        sjs[h][m] = (m < NF) ? g_sj[(b * HH + h) * NF + m] : 0.f;
    }
    __syncthreads();

    for (int i = tid; i < 10 * 512; i += 256) {
        int rr = i / 512, mm = i - rr * 512;
        int r = n0 - 1 + rr, m = mm - 1;
        float a = 0.f;
        if (r >= 0 && r < NF && m >= 0 && m < NF) {
#pragma unroll
            for (int h = 0; h < HH; h++) {
                float e = si_blk[rr][h] + sjs[h][m];
                a += (e >= 0.f) ? e : 0.01f * e;
            }
            a *= 0.25f;
        }
        am[rr][mm] = a;
    }
    __syncthreads();

    int n = n0 + wid;
    bool active = n < NF;
    float si1[HH];
#pragma unroll
    for (int h = 0; h < HH; h++) si1[h] = si_blk[wid + 1][h];

#pragma unroll
    for (int hp = 0; hp < 2; hp++) {
        int h0 = hp << 1, h1 = h0 + 1;
        const float* cc0 = g_cconv + ((size_t)h0 * NF + n) * NF;
        const float* cc1 = g_cconv + ((size_t)h1 * NF + n) * NF;
        float lg0[16], lg1[16];
        float mx0 = -1e30f, mx1 = -1e30f;

#pragma unroll
        for (int c = 0; c < 16; c++) {
            int m = (c << 5) + lane;
            float l0 = -1e30f, l1 = -1e30f;
            if (active && m < NF) {
                float st0 = cc0[m];
                float st1 = cc1[m];
#pragma unroll
                for (int rr = 0; rr < 3; rr++) {
                    float a0 = am[wid + rr][m];
                    float a1 = am[wid + rr][m + 1];
                    float a2 = am[wid + rr][m + 2];
                    st0 = fmaf(cw9[h0][rr * 3 + 0], a0, st0);
                    st0 = fmaf(cw9[h0][rr * 3 + 1], a1, st0);
                    st0 = fmaf(cw9[h0][rr * 3 + 2], a2, st0);
                    st1 = fmaf(cw9[h1][rr * 3 + 0], a0, st1);
                    st1 = fmaf(cw9[h1][rr * 3 + 1], a1, st1);
                    st1 = fmaf(cw9[h1][rr * 3 + 2], a2, st1);
                }
                float e0 = si1[h0] + sjs[h0][m];
                float e1 = si1[h1] + sjs[h1][m];
                float av0 = (e0 >= 0.f) ? e0 : 0.01f * e0;
                float av1 = (e1 >= 0.f) ? e1 : 0.01f * e1;
                l0 = fmaf(0.1f, av0, st0);
                l1 = fmaf(0.1f, av1, st1);
            }
            lg0[c] = l0; lg1[c] = l1;
            mx0 = fmaxf(mx0, l0); mx1 = fmaxf(mx1, l1);
        }

#pragma unroll
        for (int o = 16; o; o >>= 1) {
            mx0 = fmaxf(mx0, __shfl_xor_sync(0xffffffffu, mx0, o));
            mx1 = fmaxf(mx1, __shfl_xor_sync(0xffffffffu, mx1, o));
        }
        float s0 = 0.f, s1 = 0.f;
#pragma unroll
        for (int c = 0; c < 16; c++) {
            float e0 = __expf(lg0[c] - mx0);
            float e1 = __expf(lg1[c] - mx1);
            lg0[c] = e0; lg1[c] = e1;
            s0 += e0; s1 += e1;
        }
#pragma unroll
        for (int o = 16; o; o >>= 1) {
            s0 += __shfl_xor_sync(0xffffffffu, s0, o);
            s1 += __shfl_xor_sync(0xffffffffu, s1, o);
        }
        float inv0 = __frcp_rn(s0);
        float inv1 = __frcp_rn(s1);

        if (active) {
            float* d0 = A_out + ((size_t)(b * HH + h0) * NF + n) * NF;
            float* d1 = A_out + ((size_t)(b * HH + h1) * NF + n) * NF;
#pragma unroll
            for (int c = 0; c < 16; c++) {
                int m = (c << 5) + lane;
                if (m < NF) {
                    d0[m] = lg0[c] * inv0;
                    d1[m] = lg1[c] * inv1;
                }
            }
        }
    }
}

// ===========================================================================
// K3 (mma.sync bf16): out[b,n,d] = 0.25 * sum_h sum_m A[b,h,n,m]*xt[b,m,h,d]
// Block = (128n x 64d, b), single wave (128 blocks). 32 stages (4h x 8 kb of
// 64m). A fp32 cp.async double-buf -> bf16 hi/lo split; X pre-split (k1b),
// cp.async triple-buf. Warp tile 32x32: 2 m-atoms x 4 n-atoms, 3-term split.
// Padded rows: 72 halves (144B) -> conflict-free fragment LDS.
// ===========================================================================
#define K3F(p)  ((unsigned)(p) * 32768u)
#define K3AH(p) (65536u + (unsigned)(p) * 36864u)
#define K3AL(p) (65536u + (unsigned)(p) * 36864u + 18432u)
#define K3XH(q) (139264u + (unsigned)(q) * 18432u)
#define K3XL(q) (139264u + (unsigned)(q) * 18432u + 9216u)
#define K3_DSMEM (194560 + 1024)

#define MMA_BF16(Cc, Aa, Bb) asm volatile( \
    "mma.sync.aligned.m16n8k16.row.col.f32.bf16.bf16.f32 " \
    "{%0,%1,%2,%3},{%4,%5,%6,%7},{%8,%9},{%0,%1,%2,%3};" \
    : "+f"((Cc)[0]), "+f"((Cc)[1]), "+f"((Cc)[2]), "+f"((Cc)[3]) \
    : "r"((Aa)[0]), "r"((Aa)[1]), "r"((Aa)[2]), "r"((Aa)[3]), \
      "r"((Bb)[0]), "r"((Bb)[1]))

__device__ __forceinline__ void ldA4(unsigned* a, unsigned ad) {
    asm volatile("ld.shared.b32 %0, [%4];\n\tld.shared.b32 %1, [%4+1152];\n\t"
                 "ld.shared.b32 %2, [%4+16];\n\tld.shared.b32 %3, [%4+1168];"
                 : "=r"(a[0]), "=r"(a[1]), "=r"(a[2]), "=r"(a[3]) : "r"(ad));
}
__device__ __forceinline__ void ldB2(unsigned* bb, unsigned ad) {
    asm volatile("ld.shared.b32 %0, [%2];\n\tld.shared.b32 %1, [%2+16];"
                 : "=r"(bb[0]), "=r"(bb[1]) : "r"(ad));
}

__device__ __forceinline__ void k3_load(const float* __restrict__ Ag, int b, int n0,
                                        int st, int q, unsigned base) {
    int tid = threadIdx.x;
    int h = st >> 3, kb = st & 7, p = st & 1;
#pragma unroll
    for (int k = 0; k < 16; k++) {
        int gid = tid + (k << 8);               // 4096 8B chunks: A[128r][64m] fp32
        int r = gid >> 5, c = gid & 31;
        int n = n0 + r, ms = (kb << 6) + (c << 1);
        const float* src = Ag;
        int sz = 0;
        if (n < NF && ms < NF) {
            src = Ag + ((size_t)(b * HH + h) * NF + n) * NF + ms;
            sz = 8;
        }
        asm volatile("cp.async.ca.shared.global [%0], [%1], 8, %2;"
                     :: "r"(base + K3F(p) + (unsigned)(gid << 3)), "l"(src), "r"(sz));
    }
    size_t xb = (size_t)(b * HH + h) * DD * XTP + (kb << 6);
#pragma unroll
    for (int k = 0; k < 2; k++) {
        int gid = tid + (k << 8);               // 512 row-chunks x (hi,lo)
        int r = gid >> 3, sc = gid & 7;
        const uint16_t* s1 = g_xth + xb + (size_t)r * XTP + (sc << 3);
        const uint16_t* s2 = g_xtl + xb + (size_t)r * XTP + (sc << 3);
        unsigned dsto = (unsigned)(r * 144 + (sc << 4));
        asm volatile("cp.async.cg.shared.global [%0], [%1], 16, 16;"
                     :: "r"(base + K3XH(q) + dsto), "l"(s1));
        asm volatile("cp.async.cg.shared.global [%0], [%1], 16, 16;"
                     :: "r"(base + K3XL(q) + dsto), "l"(s2));
    }
    asm volatile("cp.async.commit_group;" ::: "memory");
}

__global__ __launch_bounds__(256) void k3_mma(const float* __restrict__ Ag) {
    extern __shared__ __align__(16) char dsm[];
    const int b = blockIdx.y, n0 = blockIdx.x << 7;
    const int tid = threadIdx.x, wid = tid >> 5, lane = tid & 31;
    unsigned base = ((unsigned)__cvta_generic_to_shared(dsm) + 1023u) & ~1023u;
    const int wm = wid >> 1, wn = wid & 1;      // 4 (M) x 2 (N) warps
    const int gr = lane >> 2, gq = lane & 3;

    float C[2][4][4];
#pragma unroll
    for (int i = 0; i < 2; i++)
#pragma unroll
        for (int j = 0; j < 4; j++)
#pragma unroll
            for (int k = 0; k < 4; k++) C[i][j][k] = 0.f;

    k3_load(Ag, b, n0, 0, 0, base);
    k3_load(Ag, b, n0, 1, 1, base);

    const unsigned aro = (unsigned)((wm * 32 + gr) * 144 + gq * 4);
    const unsigned bro = (unsigned)((wn * 32 + gr) * 144 + gq * 4);

    for (int t = 0; t < 32; t++) {
        const int p = t & 1, q = t % 3;
        if (t < 31) asm volatile("cp.async.wait_group 1;" ::: "memory");
        else        asm volatile("cp.async.wait_group 0;" ::: "memory");
        __syncthreads();   // stage-t data visible; mma(t-2)/convert(t-2) done

        // A: 128x64 fp32 -> bf16 hi/lo (rows padded to 144B)
#pragma unroll
        for (int k = 0; k < 16; k++) {
            int pid = tid + (k << 8);
            int r = pid >> 5, pc = pid & 31;
            float v0, v1;
            asm volatile("ld.shared.v2.f32 {%0,%1}, [%2];" : "=f"(v0), "=f"(v1)
                         : "r"(base + K3F(p) + (unsigned)(pid << 3)));
            unsigned hi, lo;
            split2(v0, v1, hi, lo);
            unsigned o = (unsigned)(r * 144 + (pc << 2));
            asm volatile("st.shared.b32 [%0], %1;" :: "r"(base + K3AH(p) + o), "r"(hi) : "memory");
            asm volatile("st.shared.b32 [%0], %1;" :: "r"(base + K3AL(p) + o), "r"(lo) : "memory");
        }
        __syncthreads();   // converts visible; F[p] free for reload

        if (t + 2 < 32) k3_load(Ag, b, n0, t + 2, (t + 2) % 3, base);

#pragma unroll
        for (int ks = 0; ks < 4; ks++) {
            const unsigned ko = (unsigned)(ks << 5);
            unsigned ah[2][4], alr[2][4], bh[4][2], bl[4][2];
#pragma unroll
            for (int ma = 0; ma < 2; ma++) {
                unsigned mo = (unsigned)(ma * 2304);   // 16 rows * 144B
                ldA4(ah[ma],  base + K3AH(p) + aro + ko + mo);
                ldA4(alr[ma], base + K3AL(p) + aro + ko + mo);
            }
#pragma unroll
            for (int j = 0; j < 4; j++) {
                unsigned no = (unsigned)(j * 1152);    // 8 rows * 144B
                ldB2(bh[j], base + K3XH(q) + bro + ko + no);
                ldB2(bl[j], base + K3XL(q) + bro + ko + no);
            }
#pragma unroll
            for (int ma = 0; ma < 2; ma++)
#pragma unroll
                for (int j = 0; j < 4; j++) {
                    MMA_BF16(C[ma][j], ah[ma],  bh[j]);
                    MMA_BF16(C[ma][j], ah[ma],  bl[j]);
                    MMA_BF16(C[ma][j], alr[ma], bh[j]);
                }
        }
    }

#pragma unroll
    for (int ma = 0; ma < 2; ma++)
#pragma unroll
        for (int j = 0; j < 4; j++) {
            int r0 = n0 + wm * 32 + ma * 16 + gr;
            int d = wn * 32 + j * 8 + gq * 2;
            if (r0 < NF) {
                float2 v = make_float2(C[ma][j][0] * 0.25f, C[ma][j][1] * 0.25f);
                *reinterpret_cast<float2*>(g_out + ((size_t)b * NF + r0) * DD + d) = v;
            }
            int r1 = r0 + 8;
            if (r1 < NF) {
                float2 v = make_float2(C[ma][j][2] * 0.25f, C[ma][j][3] * 0.25f);
                *reinterpret_cast<float2*>(g_out + ((size_t)b * NF + r1) * DD + d) = v;
            }
        }
}

// ---------------------------------------------------------------------------
// K4: g = out @ fcg_w + fcg_b; GLU; residual; LayerNorm. 8 rows/block.
// ---------------------------------------------------------------------------
__global__ void k4_glu_ln(const float* __restrict__ x,
                          const float* __restrict__ fw, const float* __restrict__ fb,
                          const float* __restrict__ lgm, const float* __restrict__ lbt,
                          float* __restrict__ y) {
    int bn0 = blockIdx.x << 3;
    int tid = threadIdx.x;
    __shared__ __align__(16) float fws[DD * 128];
    __shared__ __align__(8) float orowT[DD][10];
    __shared__ float gsh[8][128];

#pragma unroll
    for (int k = 0; k < 8; k++) {
        int f = (tid + (k << 8)) << 2;
        *reinterpret_cast<float4*>(fws + f) = *reinterpret_cast<const float4*>(fw + f);
    }
#pragma unroll
    for (int k = 0; k < 2; k++) {
        int i = tid + (k << 8);
        int rr = i >> 6, d = i & 63;
        orowT[d][rr] = g_out[(size_t)(bn0 + rr) * DD + d];
    }
    __syncthreads();

    int col = tid & 127, rh = tid >> 7;
    float fbv = fb[col];
    ull acc01 = pack2(fbv, fbv);
    ull acc23 = pack2(fbv, fbv);
#pragma unroll
    for (int d = 0; d < DD; d++) {
        float fv = fws[d * 128 + col];
        ull fv2 = pack2(fv, fv);
        ull o01 = *reinterpret_cast<const ull*>(&orowT[d][rh * 4]);
        ull o23 = *reinterpret_cast<const ull*>(&orowT[d][rh * 4 + 2]);
        fma2(acc01, o01, fv2);
        fma2(acc23, o23, fv2);
    }
    {
        float2 v01 = unpack2(acc01);
        float2 v23 = unpack2(acc23);
        gsh[rh * 4 + 0][col] = v01.x;
        gsh[rh * 4 + 1][col] = v01.y;
        gsh[rh * 4 + 2][col] = v23.x;
        gsh[rh * 4 + 3][col] = v23.y;
    }
    __syncthreads();

    int w = tid >> 5, l = tid & 31;
    int bn = bn0 + w;
    float yv0, yv1;
    {
        float a0 = gsh[w][l],      b0 = gsh[w][l + 64];
        float a1 = gsh[w][l + 32], b1 = gsh[w][l + 96];
        float s0 = 1.f / (1.f + __expf(-b0));
        float s1 = 1.f / (1.f + __expf(-b1));
        yv0 = fmaf(a0, s0, x[(size_t)bn * DD + l]);
        yv1 = fmaf(a1, s1, x[(size_t)bn * DD + l + 32]);
    }
    float s = yv0 + yv1;
#pragma unroll
    for (int o = 16; o; o >>= 1) s += __shfl_xor_sync(0xffffffffu, s, o);
    float mu = s * (1.f / 64.f);
    float d0 = yv0 - mu, d1 = yv1 - mu;
    float q = d0 * d0 + d1 * d1;
#pragma unroll
    for (int o = 16; o; o >>= 1) q += __shfl_xor_sync(0xffffffffu, q, o);
    float rs = rsqrtf(q * (1.f / 64.f) + 1e-5f);
    y[(size_t)bn * DD + l]      = d0 * rs * lgm[l]      + lbt[l];
    y[(size_t)bn * DD + l + 32] = d1 * rs * lgm[l + 32] + lbt[l + 32];
}

// ---------------------------------------------------------------------------
extern "C" void kernel_launch(void* const* d_in, const int* in_sizes, int n_in,
                              void* d_out, int out_size) {
    const float* x      = (const float*)d_in[0];
    const float* causal = (const float*)d_in[1];
    const float* W      = (const float*)d_in[2];
    const float* attw   = (const float*)d_in[3];
    const float* conv_w = (const float*)d_in[4];
    const float* conv_b = (const float*)d_in[5];
    const float* fcg_w  = (const float*)d_in[6];
    const float* fcg_b  = (const float*)d_in[7];
    const float* ln_g   = (const float*)d_in[8];
    const float* ln_b   = (const float*)d_in[9];

    float* y = (float*)d_out;
    float* A = (float*)d_out + (size_t)BB * NF * DD;   // (y, A) flattened in order

    cudaFuncSetAttribute(k3_mma, cudaFuncAttributeMaxDynamicSharedMemorySize, K3_DSMEM);

    k1_proj<<<(BB * NF) / 8, 256>>>(x, W, attw);
    k1b_split<<<dim3(8, BB * HH), 256>>>();
    k2a_cconv<<<NF, 256>>>(causal, conv_w, conv_b);
    k2_attn<<<dim3(64, BB), 256>>>(conv_w, A);
    k3_mma<<<dim3(4, BB), 256, K3_DSMEM>>>(A);
    k4_glu_ln<<<(BB * NF) / 8, 256>>>(x, fcg_w, fcg_b, ln_g, ln_b, y);
}